// round 15
// baseline (speedup 1.0000x reference)
#include <cuda_runtime.h>
#include <cuda_bf16.h>
#include <math.h>
#include <stdint.h>

// ---------------- problem constants ----------------
#define BB      4
#define LL      4096
#define DMODEL  1024
#define DINNER  2048
#define NHEADS  16
#define DSTATE  64
#define PROJ    4256
#define MROWS   (BB*LL)          // 16384
#define NPAD1   4352             // 34 * 128
#define K3_1    (3*DMODEL)       // 3072
#define K3_2    (3*DINNER)       // 6144

typedef unsigned long long u64;

// ---------------- scratch (__device__ globals; no runtime alloc) -------------
__device__ __align__(16) float g_xs   [(size_t)MROWS * DINNER];   // silu(x)
__device__ __align__(16) float g_sz   [(size_t)MROWS * DINNER];   // silu(z)
__device__ __align__(16) float g_tail [(size_t)MROWS * 160];      // B,C,dt,lam raw
__device__ __align__(16) float g_Bc   [(size_t)MROWS * DSTATE];
__device__ __align__(16) float g_Cc   [(size_t)MROWS * DSTATE];
__device__ __align__(16) float g_coef [(size_t)MROWS * NHEADS * 4];
__device__ __align__(16) float g_theta[(size_t)MROWS * 32];
__device__ __align__(16) float g_phi  [(size_t)MROWS * 32];
__device__ __align__(16) float g_csum [(size_t)BB * 64 * 32];
// K-tripled bf16 operands: A'' = [hi, lo, hi], B'' = [hi, hi, lo]
__device__ __align__(16) __nv_bfloat16 g_a3 [(size_t)MROWS * K3_1];
__device__ __align__(16) __nv_bfloat16 g_yz3[(size_t)MROWS * K3_2];
__device__ __align__(16) __nv_bfloat16 g_w31[(size_t)NPAD1 * K3_1];
__device__ __align__(16) __nv_bfloat16 g_w32[(size_t)DMODEL * K3_2];

// ---------------- PTX helpers --------------------------------------------------
__device__ __forceinline__ uint32_t s2u(const void* p)
{
    uint32_t r;
    asm("{ .reg .u64 t; cvta.to.shared.u64 t, %1; cvt.u32.u64 %0, t; }"
        : "=r"(r) : "l"(p));
    return r;
}
__device__ __forceinline__ void cp16(uint32_t d, const void* s)
{
    asm volatile("cp.async.cg.shared.global [%0], [%1], 16;" :: "r"(d), "l"(s));
}
#define CP_COMMIT() asm volatile("cp.async.commit_group;" ::: "memory")
#define CP_WAIT1()  asm volatile("cp.async.wait_group 1;"  ::: "memory")

__device__ __forceinline__ void ldm4(uint32_t* r, uint32_t a)
{
    asm volatile("ldmatrix.sync.aligned.m8n8.x4.shared.b16 {%0,%1,%2,%3}, [%4];"
        : "=r"(r[0]), "=r"(r[1]), "=r"(r[2]), "=r"(r[3]) : "r"(a));
}
__device__ __forceinline__ void mma16816(float* d, const uint32_t* a, const uint32_t* b)
{
    asm volatile("mma.sync.aligned.m16n8k16.row.col.f32.bf16.bf16.f32 "
        "{%0,%1,%2,%3}, {%4,%5,%6,%7}, {%8,%9}, {%0,%1,%2,%3};"
        : "+f"(d[0]), "+f"(d[1]), "+f"(d[2]), "+f"(d[3])
        : "r"(a[0]), "r"(a[1]), "r"(a[2]), "r"(a[3]), "r"(b[0]), "r"(b[1]));
}
__device__ __forceinline__ float silu1(float v)
{
    return v / (1.f + expf(-v));
}
__device__ __forceinline__ uint32_t packbf2(float a, float b)
{
    __nv_bfloat162 t;
    t.x = __float2bfloat16(a);
    t.y = __float2bfloat16(b);
    return *(uint32_t*)&t;
}
// ---- packed f32x2 (Blackwell sm_100+) ----
__device__ __forceinline__ u64 pk2(float x, float y)
{
    u64 r;
    asm("mov.b64 %0, {%1, %2};" : "=l"(r) : "f"(x), "f"(y));
    return r;
}
__device__ __forceinline__ void upk2(float& x, float& y, u64 v)
{
    asm("mov.b64 {%0, %1}, %2;" : "=f"(x), "=f"(y) : "l"(v));
}
__device__ __forceinline__ u64 fma2_(u64 a, u64 b, u64 c)
{
    u64 d;
    asm("fma.rn.f32x2 %0, %1, %2, %3;" : "=l"(d) : "l"(a), "l"(b), "l"(c));
    return d;
}
__device__ __forceinline__ u64 mul2_(u64 a, u64 b)
{
    u64 d;
    asm("mul.rn.f32x2 %0, %1, %2;" : "=l"(d) : "l"(a), "l"(b));
    return d;
}
__device__ __forceinline__ u64 add2_(u64 a, u64 b)
{
    u64 d;
    asm("add.rn.f32x2 %0, %1, %2;" : "=l"(d) : "l"(a), "l"(b));
    return d;
}

// ---------------- theta = u @ theta_w  (blocked; tw cached in smem) -------------
#define THETA_SMEM ((32768 + 128 * 68) * 4)
__global__ void __launch_bounds__(256) k_theta(const float* __restrict__ u,
                                               const float* __restrict__ tw)
{
    extern __shared__ float ts[];
    float* stw = ts;            // 32768 floats
    float* su  = ts + 32768;    // 128 x 68 (pad 4)
    int m0 = blockIdx.x * 128, tid = threadIdx.x;
    #pragma unroll
    for (int i = 0; i < 32; ++i) {
        int idx = tid + i * 256;
        *(float4*)(stw + idx * 4) = *(const float4*)(tw + idx * 4);
    }
    int row = tid >> 1, cb = (tid & 1) * 16;
    float acc[16];
    #pragma unroll
    for (int c = 0; c < 16; ++c) acc[c] = 0.f;

    for (int kc = 0; kc < 16; ++kc) {
        __syncthreads();
        #pragma unroll
        for (int j = 0; j < 8; ++j) {
            int idx4 = tid + j * 256;
            int rw = idx4 >> 4, cc = (idx4 & 15) * 4;
            *(float4*)(su + rw * 68 + cc) =
                *(const float4*)(u + (size_t)(m0 + rw) * 1024 + kc * 64 + cc);
        }
        __syncthreads();
        #pragma unroll 8
        for (int kk = 0; kk < 64; ++kk) {
            float xv = su[row * 68 + kk];
            const float* twp = stw + (kc * 64 + kk) * 32 + cb;
            float4 w0 = *(const float4*)(twp);
            float4 w1 = *(const float4*)(twp + 4);
            float4 w2 = *(const float4*)(twp + 8);
            float4 w3 = *(const float4*)(twp + 12);
            acc[0]  = fmaf(xv, w0.x, acc[0]);  acc[1]  = fmaf(xv, w0.y, acc[1]);
            acc[2]  = fmaf(xv, w0.z, acc[2]);  acc[3]  = fmaf(xv, w0.w, acc[3]);
            acc[4]  = fmaf(xv, w1.x, acc[4]);  acc[5]  = fmaf(xv, w1.y, acc[5]);
            acc[6]  = fmaf(xv, w1.z, acc[6]);  acc[7]  = fmaf(xv, w1.w, acc[7]);
            acc[8]  = fmaf(xv, w2.x, acc[8]);  acc[9]  = fmaf(xv, w2.y, acc[9]);
            acc[10] = fmaf(xv, w2.z, acc[10]); acc[11] = fmaf(xv, w2.w, acc[11]);
            acc[12] = fmaf(xv, w3.x, acc[12]); acc[13] = fmaf(xv, w3.y, acc[13]);
            acc[14] = fmaf(xv, w3.z, acc[14]); acc[15] = fmaf(xv, w3.w, acc[15]);
        }
    }
    float* out = g_theta + (size_t)(m0 + row) * 32 + cb;
    #pragma unroll
    for (int c = 0; c < 16; c += 4) {
        float4 v = {acc[c], acc[c+1], acc[c+2], acc[c+3]};
        *(float4*)(out + c) = v;
    }
}

// ---------------- layernorm + K3 hi/lo pack -------------------------------------
__global__ void __launch_bounds__(256) k_ln(const float* __restrict__ u,
        const float* __restrict__ gscale, const float* __restrict__ gbias)
{
    __shared__ float rsum[8], rsq[8];
    __shared__ float s_mu, s_rs;
    int m = blockIdx.x, tid = threadIdx.x;
    const float* ur = u + (size_t)m * 1024 + tid * 4;
    float4 v = *(const float4*)ur;
    float s = v.x + v.y + v.z + v.w;
    float q = v.x*v.x + v.y*v.y + v.z*v.z + v.w*v.w;
    #pragma unroll
    for (int o = 16; o; o >>= 1) {
        s += __shfl_xor_sync(0xffffffffu, s, o);
        q += __shfl_xor_sync(0xffffffffu, q, o);
    }
    int lane = tid & 31, wid = tid >> 5;
    if (lane == 0) { rsum[wid] = s; rsq[wid] = q; }
    __syncthreads();
    if (tid == 0) {
        float S = 0.f, Q = 0.f;
        #pragma unroll
        for (int i = 0; i < 8; i++) { S += rsum[i]; Q += rsq[i]; }
        float mu  = S * (1.f / 1024.f);
        float var = Q * (1.f / 1024.f) - mu * mu;
        s_mu = mu;
        s_rs = rsqrtf(var + 1e-6f);
    }
    __syncthreads();
    float mu = s_mu, rs = s_rs;
    float4 sc = *(const float4*)(gscale + tid * 4);
    float4 bi = *(const float4*)(gbias  + tid * 4);
    float o0 = (v.x - mu) * rs * sc.x + bi.x;
    float o1 = (v.y - mu) * rs * sc.y + bi.y;
    float o2 = (v.z - mu) * rs * sc.z + bi.z;
    float o3 = (v.w - mu) * rs * sc.w + bi.w;
    __nv_bfloat16 h0 = __float2bfloat16(o0), h1 = __float2bfloat16(o1);
    __nv_bfloat16 h2 = __float2bfloat16(o2), h3 = __float2bfloat16(o3);
    __nv_bfloat162 hi01 = {h0, h1}, hi23 = {h2, h3};
    __nv_bfloat162 lo01 = {__float2bfloat16(o0 - __bfloat162float(h0)),
                           __float2bfloat16(o1 - __bfloat162float(h1))};
    __nv_bfloat162 lo23 = {__float2bfloat16(o2 - __bfloat162float(h2)),
                           __float2bfloat16(o3 - __bfloat162float(h3))};
    __nv_bfloat16* row = g_a3 + (size_t)m * K3_1;
    *(__nv_bfloat162*)(row + tid * 4)            = hi01;
    *(__nv_bfloat162*)(row + tid * 4 + 2)        = hi23;
    *(__nv_bfloat162*)(row + 1024 + tid * 4)     = lo01;
    *(__nv_bfloat162*)(row + 1024 + tid * 4 + 2) = lo23;
    *(__nv_bfloat162*)(row + 2048 + tid * 4)     = hi01;
    *(__nv_bfloat162*)(row + 2048 + tid * 4 + 2) = hi23;
}

// ---------------- weight transpose + K3 split: T[n][3K] = [hi, hi, lo] ---------
__global__ void k_tsplit(const float* __restrict__ W, int K, int N,
                         __nv_bfloat16* __restrict__ T)
{
    __shared__ float t[32][33];
    int nb = blockIdx.x * 32, kb = blockIdx.y * 32;
    int x = threadIdx.x, y = threadIdx.y;   // 32 x 8
    #pragma unroll
    for (int i = 0; i < 32; i += 8) {
        int k = kb + y + i, n = nb + x;
        t[y + i][x] = (n < N) ? W[(size_t)k * N + n] : 0.f;
    }
    __syncthreads();
    #pragma unroll
    for (int i = 0; i < 32; i += 8) {
        int n = nb + y + i, k = kb + x;
        float v = t[x][y + i];
        __nv_bfloat16 h = __float2bfloat16(v);
        __nv_bfloat16 l = __float2bfloat16(v - __bfloat162float(h));
        __nv_bfloat16* row = T + (size_t)n * 3 * K;
        row[k]         = h;
        row[K + k]     = h;
        row[2 * K + k] = l;
    }
}

// ---------------- mma.sync bf16 GEMM (K3, 128x128 CTA, 64x64 warp, BK=64) -------
// 128 threads = 4 warps (2m x 2n). Register double-buffered ldsm fragments.
// MODE 0: fused proj epilogue; MODE 1: C = result + ADD
#define GSTAGE 32768
#define GSMEM  (3 * GSTAGE)

template<int MODE>
__global__ void __launch_bounds__(128, 2)
k_gemm_mma(const __nv_bfloat16* __restrict__ A, const __nv_bfloat16* __restrict__ B,
           const float* __restrict__ ADD, float* __restrict__ C, int N, int Kp)
{
    extern __shared__ char sm[];
    uint32_t smu = s2u(sm);
    int tid = threadIdx.x, wid = tid >> 5, lane = tid & 31;
    int n0 = blockIdx.x * 128, m0 = blockIdx.y * 128;
    int KT = Kp >> 6;

    auto issue = [&](int kt, int slot) {
        uint32_t st = smu + slot * GSTAGE;
        size_t k0 = (size_t)kt * 64;
        #pragma unroll
        for (int t = 0; t < 8; ++t) {
            int idx = tid + t * 128;
            int rw = idx >> 3, c = idx & 7;
            uint32_t sw = (uint32_t)(rw * 128) + (uint32_t)((c ^ (rw & 7)) << 4);
            cp16(st + sw, A + (size_t)(m0 + rw) * Kp + k0 + c * 8);
        }
        #pragma unroll
        for (int t = 0; t < 8; ++t) {
            int idx = tid + t * 128;
            int rw = idx >> 3, c = idx & 7;
            uint32_t sw = (uint32_t)(rw * 128) + (uint32_t)((c ^ (rw & 7)) << 4);
            cp16(st + 16384 + sw, B + (size_t)(n0 + rw) * Kp + k0 + c * 8);
        }
    };

    issue(0, 0); CP_COMMIT();
    issue(1, 1); CP_COMMIT();

    float d[4][8][4];
    #pragma unroll
    for (int i = 0; i < 4; i++)
        #pragma unroll
        for (int j = 0; j < 8; j++)
            #pragma unroll
            for (int e = 0; e < 4; e++) d[i][j][e] = 0.f;

    int mo = (wid >> 1) * 64, no = (wid & 1) * 64;
    uint32_t afr[2][4][4], bfr[2][4][4];

    auto ldfr = [&](int ks, uint32_t sA, uint32_t sB,
                    uint32_t (*af)[4], uint32_t (*bf)[4]) {
        int cA = ks * 2 + (lane >> 4);
        #pragma unroll
        for (int ma = 0; ma < 4; ++ma) {
            int r = mo + ma * 16 + (lane & 15);
            ldm4(af[ma], sA + (uint32_t)(r * 128) + (uint32_t)((cA ^ (r & 7)) << 4));
        }
        int cB = ks * 2 + ((lane >> 3) & 1);
        #pragma unroll
        for (int nb = 0; nb < 4; ++nb) {
            int r = no + nb * 16 + (lane & 7) + (((lane >> 4) & 1) << 3);
            ldm4(bf[nb], sB + (uint32_t)(r * 128) + (uint32_t)((cB ^ (r & 7)) << 4));
        }
    };

    for (int kt = 0; kt < KT; ++kt) {
        CP_WAIT1();
        __syncthreads();
        if (kt + 2 < KT) issue(kt + 2, (kt + 2) % 3);
        CP_COMMIT();

        uint32_t sA = smu + (kt % 3) * GSTAGE;
        uint32_t sB = sA + 16384;
        ldfr(0, sA, sB, afr[0], bfr[0]);
        #pragma unroll
        for (int ks = 0; ks < 4; ++ks) {
            int cur = ks & 1;
            if (ks < 3)
                ldfr(ks + 1, sA, sB, afr[cur ^ 1], bfr[cur ^ 1]);
            #pragma unroll
            for (int mi = 0; mi < 4; ++mi)
                #pragma unroll
                for (int ni = 0; ni < 8; ++ni)
                    mma16816(d[mi][ni], afr[cur][mi],
                             &bfr[cur][ni >> 1][(ni & 1) * 2]);
        }
    }

    // epilogue
    #pragma unroll
    for (int mi = 0; mi < 4; ++mi) {
        int r0 = m0 + mo + mi * 16 + (lane >> 2);
        #pragma unroll
        for (int ni = 0; ni < 8; ++ni) {
            int col = n0 + no + ni * 8 + (lane & 3) * 2;
            #pragma unroll
            for (int half = 0; half < 2; ++half) {
                int row = r0 + half * 8;
                float2 v = {d[mi][ni][half * 2], d[mi][ni][half * 2 + 1]};
                if (MODE == 0) {
                    if (col < 2048) {
                        float2 o = {silu1(v.x), silu1(v.y)};
                        *(float2*)(g_xs + (size_t)row * 2048 + col) = o;
                    } else if (col < 4096) {
                        float2 o = {silu1(v.x), silu1(v.y)};
                        *(float2*)(g_sz + (size_t)row * 2048 + col - 2048) = o;
                    } else if (col < 4256) {
                        *(float2*)(g_tail + (size_t)row * 160 + col - 4096) = v;
                    }
                } else {
                    if (col < N) {
                        float2 a2 = *(const float2*)(ADD + (size_t)row * N + col);
                        v.x += a2.x; v.y += a2.y;
                        *(float2*)(C + (size_t)row * N + col) = v;
                    }
                }
            }
        }
    }
}

// ---------------- per-row prep (tail only) --------------------------------------
__global__ void __launch_bounds__(96) k_prep(const float* __restrict__ A_log,
        const float* __restrict__ dt_bias,
        const float* __restrict__ bcB, const float* __restrict__ bcC,
        const float* __restrict__ Bbias, const float* __restrict__ Cbias)
{
    int m = blockIdx.x, tid = threadIdx.x;
    const float* tail = g_tail + (size_t)m * 160;
    __shared__ float s_dts;

    int lane = tid & 31, wid = tid >> 5;
    if (wid == 0) {
        float b0 = tail[lane], b1 = tail[32 + lane];
        float ss = b0 * b0 + b1 * b1;
        #pragma unroll
        for (int o = 16; o; o >>= 1) ss += __shfl_xor_sync(0xffffffffu, ss, o);
        float r = rsqrtf(ss * (1.f / 64.f) + 1e-6f);
        g_Bc[(size_t)m * 64 + lane]      = b0 * r * bcB[lane]      + Bbias[lane];
        g_Bc[(size_t)m * 64 + 32 + lane] = b1 * r * bcB[32 + lane] + Bbias[32 + lane];
    } else if (wid == 1) {
        float b0 = tail[64 + lane], b1 = tail[96 + lane];
        float ss = b0 * b0 + b1 * b1;
        #pragma unroll
        for (int o = 16; o; o >>= 1) ss += __shfl_xor_sync(0xffffffffu, ss, o);
        float r = rsqrtf(ss * (1.f / 64.f) + 1e-6f);
        g_Cc[(size_t)m * 64 + lane]      = b0 * r * bcC[lane]      + Cbias[lane];
        g_Cc[(size_t)m * 64 + 32 + lane] = b1 * r * bcC[32 + lane] + Cbias[32 + lane];
    } else {
        float dt = 0.f;
        if (lane < 16) {
            float x = tail[128 + lane] + dt_bias[lane];
            dt = (x > 20.f) ? x : log1pf(expf(x));
            float lamr = tail[144 + lane];
            float lam = 1.f / (1.f + expf(-lamr));
            float a = expf(-expf(A_log[lane]) * dt);
            size_t o = ((size_t)m * 16 + lane) * 4;
            g_coef[o]     = a;
            g_coef[o + 1] = dt * lam;
            g_coef[o + 2] = dt * (1.f - lam) * a;
            g_coef[o + 3] = 0.f;
        }
        float s = dt;
        #pragma unroll
        for (int o = 16; o; o >>= 1) s += __shfl_xor_sync(0xffffffffu, s, o);
        if (lane == 0) s_dts = s * (1.f / 16.f);
    }
    __syncthreads();
    if (tid < 32)
        g_phi[(size_t)m * 32 + tid] = s_dts * g_theta[(size_t)m * 32 + tid];
}

// ---------------- 3-phase cumsum (phase 3 fused with RoPE) ----------------------
__global__ void k_cs_chunk()
{
    int b = blockIdx.x >> 6, ch = blockIdx.x & 63;
    int c = threadIdx.x;
    size_t base = (((size_t)b * 4096) + (size_t)ch * 64) * 32 + c;
    float acc = 0.f;
    #pragma unroll 8
    for (int l = 0; l < 64; ++l) {
        acc += g_phi[base + (size_t)l * 32];
        g_phi[base + (size_t)l * 32] = acc;
    }
    g_csum[((size_t)(b * 64 + ch)) * 32 + c] = acc;
}
__global__ void k_cs_scan()
{
    int tid = threadIdx.x;
    int b = tid >> 5, c = tid & 31;
    float acc = 0.f;
    #pragma unroll 8
    for (int ch = 0; ch < 64; ++ch) {
        size_t o = ((size_t)(b * 64 + ch)) * 32 + c;
        float t = g_csum[o];
        g_csum[o] = acc;
        acc += t;
    }
}
__global__ void k_cs_add_rope()
{
    int b = blockIdx.x >> 6, ch = blockIdx.x & 63;
    __shared__ float off[32];
    if (threadIdx.x < 32)
        off[threadIdx.x] = g_csum[((size_t)(b * 64 + ch)) * 32 + threadIdx.x];
    __syncthreads();
    size_t mbase = (size_t)b * 4096 + (size_t)ch * 64;
    for (int e = threadIdx.x; e < 2048; e += 256) {
        int r = e >> 5, c = e & 31;
        size_t m = mbase + r;
        float ph = g_phi[m * 32 + c] + off[c];
        float cc = cosf(ph), ss = sinf(ph);
        size_t o = m * 64 + c;
        float xr = g_Bc[o], xi = g_Bc[o + 32];
        g_Bc[o]      = xr * cc - xi * ss;
        g_Bc[o + 32] = xr * ss + xi * cc;
        xr = g_Cc[o]; xi = g_Cc[o + 32];
        g_Cc[o]      = xr * cc - xi * ss;
        g_Cc[o + 32] = xr * ss + xi * cc;
    }
}

// ---------------- SSD scan + gate + bf16 K3 pack (4p x 8n, s-substitution) ------
// grid 128 = (b:4, h:16, pg2:2); 128 threads: pq = tid>>3 (16), nsub = tid&7.
#define SCHUNK 32
#define ST2_F  8320
#define SCAN_SMEM ((2 * ST2_F + 2048) * 4)   // 74752 bytes

__global__ void __launch_bounds__(128) k_scan(const float* __restrict__ Dv)
{
    extern __shared__ float sf[];
    uint32_t smu = s2u(sf);
    int bx = blockIdx.x;
    int pg2 = bx & 1, h = (bx >> 1) & 15, b = bx >> 5;
    int tid = threadIdx.x;
    int nsub = tid & 7, pq = tid >> 3;
    size_t mb = (size_t)b * 4096;
    const float* Bg = g_Bc + mb * 64;
    const float* Cg = g_Cc + mb * 64;
    const float* Xg = g_xs + mb * 2048 + h * 128 + pg2 * 64;
    const float* Zg = g_sz + mb * 2048 + h * 128 + pg2 * 64;
    const float* Kg = g_coef + (mb * 16 + h) * 4;
    float Dh = Dv[h];
    int jbase = h * 128 + pg2 * 64;

    auto load_chunk = [&](int c, int slot) {
        int t0 = c * SCHUNK;
        uint32_t sb = smu + slot * ST2_F * 4;
        #pragma unroll
        for (int i = 0; i < 4; ++i) {
            int idx = tid + i * 128;
            int t = idx >> 4, seg = idx & 15;
            cp16(sb + (uint32_t)(t * 64 + seg * 4) * 4,
                 Bg + (size_t)(t0 + t) * 64 + seg * 4);
        }
        #pragma unroll
        for (int i = 0; i < 4; ++i) {
            int idx = tid + i * 128;
            int t = idx >> 4, seg = idx & 15;
            cp16(sb + (uint32_t)(2048 + t * 64 + seg * 4) * 4,
                 Cg + (size_t)(t0 + t) * 64 + seg * 4);
        }
        #pragma unroll
        for (int i = 0; i < 4; ++i) {
            int idx = tid + i * 128;
            int t = idx >> 4, seg = idx & 15;
            cp16(sb + (uint32_t)(4096 + t * 64 + seg * 4) * 4,
                 Xg + (size_t)(t0 + t) * 2048 + seg * 4);
        }
        #pragma unroll
        for (int i = 0; i < 4; ++i) {
            int idx = tid + i * 128;
            int t = idx >> 4, seg = idx & 15;
            cp16(sb + (uint32_t)(6144 + t * 64 + seg * 4) * 4,
                 Zg + (size_t)(t0 + t) * 2048 + seg * 4);
        }
        if (tid < SCHUNK)
            cp16(sb + (uint32_t)(8192 + tid * 4) * 4,
                 Kg + (size_t)(t0 + tid) * 64);
    };

    u64 s2[4][4], Bp2[4];
    #pragma unroll
    for (int p = 0; p < 4; ++p)
        #pragma unroll
        for (int i = 0; i < 4; ++i) s2[p][i] = 0ull;
    #pragma unroll
    for (int i = 0; i < 4; ++i) Bp2[i] = 0ull;
    float4 xprev = {0.f, 0.f, 0.f, 0.f};
    float alpha_prev = 0.f;
    float* ybuf = sf + 2 * ST2_F;

    load_chunk(0, 0); CP_COMMIT();
    load_chunk(1, 1); CP_COMMIT();

    const int NCHUNK = LL / SCHUNK;   // 128
    for (int c = 0; c < NCHUNK; ++c) {
        int slot = c & 1;
        const float* st = sf + slot * ST2_F;
        CP_WAIT1();
        __syncthreads();
        #pragma unroll 2
        for (int t = 0; t < SCHUNK; ++t) {
            ulonglong2 B01 = *(const ulonglong2*)(st + t * 64 + nsub * 8);
            ulonglong2 B23 = *(const ulonglong2*)(st + t * 64 + nsub * 8 + 4);
            ulonglong2 C01 = *(const ulonglong2*)(st + 2048 + t * 64 + nsub * 8);
            ulonglong2 C23 = *(const ulonglong2*)(st + 2048 + t * 64 + nsub * 8 + 4);
            float4 cf = *(const float4*)(st + 8192 + t * 4);
            float4 x4 = *(const float4*)(st + 4096 + t * 64 + pq * 4);
            u64 Bn[4] = {B01.x, B01.y, B23.x, B23.y};
            u64 Cn[4] = {C01.x, C01.y, C23.x, C23.y};

            float delta = fmaf(cf.x, alpha_prev, cf.z);
            u64 ca2 = pk2(cf.x, cf.x);
            u64 e2[4];
            e2[0] = pk2(delta * xprev.x, delta * xprev.x);
            e2[1] = pk2(delta * xprev.y, delta * xprev.y);
            e2[2] = pk2(delta * xprev.z, delta * xprev.z);
            e2[3] = pk2(delta * xprev.w, delta * xprev.w);

            u64 cb2 = 0ull;
            u64 acc2[4] = {0ull, 0ull, 0ull, 0ull};
            #pragma unroll
            for (int i = 0; i < 4; ++i) {
                cb2 = fma2_(Bn[i], Cn[i], cb2);
                #pragma unroll
                for (int p = 0; p < 4; ++p) {
                    s2[p][i] = fma2_(ca2, s2[p][i], mul2_(e2[p], Bp2[i]));
                    acc2[p] = fma2_(s2[p][i], Cn[i], acc2[p]);
                }
                Bp2[i] = Bn[i];
            }
            float a0l, a0h, a1l, a1h, a2l, a2h, a3l, a3h, cbl, cbh;
            upk2(a0l, a0h, acc2[0]); upk2(a1l, a1h, acc2[1]);
            upk2(a2l, a2h, acc2[2]); upk2(a3l, a3h, acc2[3]);
            upk2(cbl, cbh, cb2);
            u64 q01 = pk2(a0l + a0h, a1l + a1h);
            u64 q23 = pk2(a2l + a2h, a3l + a3h);
            float cb = cbl + cbh;
            #pragma unroll
            for (int o = 1; o < 8; o <<= 1) {
                q01 = add2_(q01, __shfl_xor_sync(0xffffffffu, q01, o));
                q23 = add2_(q23, __shfl_xor_sync(0xffffffffu, q23, o));
                cb += __shfl_xor_sync(0xffffffffu, cb, o);
            }
            if (nsub == 0) {
                float y0, y1, y2, y3;
                upk2(y0, y1, q01);
                upk2(y2, y3, q23);
                float axcb = cf.y * cb;
                float4 z4 = *(const float4*)(st + 6144 + t * 64 + pq * 4);
                float4 yo;
                yo.x = (y0 + x4.x * (axcb + Dh)) * z4.x;
                yo.y = (y1 + x4.y * (axcb + Dh)) * z4.y;
                yo.z = (y2 + x4.z * (axcb + Dh)) * z4.z;
                yo.w = (y3 + x4.w * (axcb + Dh)) * z4.w;
                *(float4*)(ybuf + t * 64 + pq * 4) = yo;
            }
            xprev = x4;
            alpha_prev = cf.y;
        }
        __syncthreads();
        #pragma unroll
        for (int i = 0; i < 4; ++i) {
            int idx = tid + i * 128;
            int t = idx >> 4, p0 = (idx & 15) * 4;
            float4 y4 = *(const float4*)(ybuf + t * 64 + p0);
            uint32_t h01 = packbf2(y4.x, y4.y);
            uint32_t h23 = packbf2(y4.z, y4.w);
            __nv_bfloat162 hv01 = *(__nv_bfloat162*)&h01;
            __nv_bfloat162 hv23 = *(__nv_bfloat162*)&h23;
            uint32_t l01 = packbf2(y4.x - __bfloat162float(hv01.x),
                                   y4.y - __bfloat162float(hv01.y));
            uint32_t l23 = packbf2(y4.z - __bfloat162float(hv23.x),
                                   y4.w - __bfloat162float(hv23.y));
            size_t row = mb + (size_t)c * SCHUNK + t;
            __nv_bfloat16* rp = g_yz3 + row * K3_2 + jbase + p0;
            uint2 H = {h01, h23}, L = {l01, l23};
            *(uint2*)rp          = H;
            *(uint2*)(rp + 2048) = L;
            *(uint2*)(rp + 4096) = H;
        }
        if (c + 2 < NCHUNK) load_chunk(c + 2, slot);
        CP_COMMIT();
    }
}

// ---------------- host launcher --------------------------------------------------
template<typename T>
static T* sym_addr(const void* s)
{
    void* p = nullptr;
    cudaGetSymbolAddress(&p, s);
    return (T*)p;
}

extern "C" void kernel_launch(void* const* d_in, const int* in_sizes, int n_in,
                              void* d_out, int out_size)
{
    const float* u          = (const float*)d_in[0];
    const float* norm_scale = (const float*)d_in[1];
    const float* norm_bias  = (const float*)d_in[2];
    const float* in_proj_w  = (const float*)d_in[3];
    const float* A_log      = (const float*)d_in[4];
    const float* dt_bias    = (const float*)d_in[5];
    const float* bcB_scale  = (const float*)d_in[6];
    const float* bcC_scale  = (const float*)d_in[7];
    const float* B_bias     = (const float*)d_in[8];
    const float* C_bias     = (const float*)d_in[9];
    const float* theta_w    = (const float*)d_in[10];
    const float* Dv         = (const float*)d_in[11];
    const float* out_proj_w = (const float*)d_in[12];
    float* out = (float*)d_out;

    __nv_bfloat16* p_a3  = sym_addr<__nv_bfloat16>(g_a3);
    __nv_bfloat16* p_yz3 = sym_addr<__nv_bfloat16>(g_yz3);
    __nv_bfloat16* p_w31 = sym_addr<__nv_bfloat16>(g_w31);
    __nv_bfloat16* p_w32 = sym_addr<__nv_bfloat16>(g_w32);

    static bool attr_done = false;
    if (!attr_done) {
        cudaFuncSetAttribute(k_gemm_mma<0>,
            cudaFuncAttributeMaxDynamicSharedMemorySize, GSMEM);
        cudaFuncSetAttribute(k_gemm_mma<1>,
            cudaFuncAttributeMaxDynamicSharedMemorySize, GSMEM);
        cudaFuncSetAttribute(k_scan,
            cudaFuncAttributeMaxDynamicSharedMemorySize, SCAN_SMEM);
        cudaFuncSetAttribute(k_theta,
            cudaFuncAttributeMaxDynamicSharedMemorySize, THETA_SMEM);
        attr_done = true;
    }

    // 1. theta = u @ theta_w (blocked, tw cached in smem)
    k_theta<<<MROWS / 128, 256, THETA_SMEM>>>(u, theta_w);
    // 2. layernorm + K3 hi/lo pack
    k_ln<<<MROWS, 256>>>(u, norm_scale, norm_bias);
    // 3. weight transpose + K3 pack
    k_tsplit<<<dim3(NPAD1 / 32, DMODEL / 32), dim3(32, 8)>>>(
        in_proj_w, DMODEL, PROJ, p_w31);
    k_tsplit<<<dim3(DMODEL / 32, DINNER / 32), dim3(32, 8)>>>(
        out_proj_w, DINNER, DMODEL, p_w32);
    // 4. proj GEMM (K3, 64x64 warp tiles, reg double-buffer, fused epilogue)
    k_gemm_mma<0><<<dim3(NPAD1 / 128, MROWS / 128), 128, GSMEM>>>(
        p_a3, p_w31, nullptr, nullptr, PROJ, K3_1);
    // 5. tail prep
    k_prep<<<MROWS, 96>>>(A_log, dt_bias, bcB_scale, bcC_scale, B_bias, C_bias);
    // 6. cumsum(phi) + fused RoPE
    k_cs_chunk<<<BB * 64, 32>>>();
    k_cs_scan<<<1, 128>>>();
    k_cs_add_rope<<<BB * 64, 256>>>();
    // 7. SSD scan + gate + pack (4p x 8n; 128 blocks)
    k_scan<<<BB * NHEADS * 2, 128, SCAN_SMEM>>>(Dv);
    // 8. out = yz @ out_proj_w + u (K3, 64x64 warp tiles, reg double-buffer)
    k_gemm_mma<1><<<dim3(DMODEL / 128, MROWS / 128), 128, GSMEM>>>(
        p_yz3, p_w32, u, out, DMODEL, K3_2);
}

// round 16
// speedup vs baseline: 1.0334x; 1.0334x over previous
#include <cuda_runtime.h>
#include <cuda_bf16.h>
#include <math.h>
#include <stdint.h>

// ---------------- problem constants ----------------
#define BB      4
#define LL      4096
#define DMODEL  1024
#define DINNER  2048
#define NHEADS  16
#define DSTATE  64
#define PROJ    4256
#define MROWS   (BB*LL)          // 16384
#define NPAD1   4352             // 34 * 128
#define K3_1    (3*DMODEL)       // 3072
#define K3_2    (3*DINNER)       // 6144

typedef unsigned long long u64;

// ---------------- scratch (__device__ globals; no runtime alloc) -------------
__device__ __align__(16) float g_xs   [(size_t)MROWS * DINNER];   // silu(x)
__device__ __align__(16) float g_sz   [(size_t)MROWS * DINNER];   // silu(z)
__device__ __align__(16) float g_tail [(size_t)MROWS * 160];      // B,C,dt,lam raw
__device__ __align__(16) float g_Bc   [(size_t)MROWS * DSTATE];
__device__ __align__(16) float g_Cc   [(size_t)MROWS * DSTATE];
__device__ __align__(16) float g_coef [(size_t)MROWS * NHEADS * 4];
__device__ __align__(16) float g_theta[(size_t)MROWS * 32];
__device__ __align__(16) float g_phi  [(size_t)MROWS * 32];
__device__ __align__(16) float g_csum [(size_t)BB * 64 * 32];
// K-tripled bf16 operands: A'' = [hi, lo, hi], B'' = [hi, hi, lo]
__device__ __align__(16) __nv_bfloat16 g_a3 [(size_t)MROWS * K3_1];
__device__ __align__(16) __nv_bfloat16 g_yz3[(size_t)MROWS * K3_2];
__device__ __align__(16) __nv_bfloat16 g_w31[(size_t)NPAD1 * K3_1];
__device__ __align__(16) __nv_bfloat16 g_w32[(size_t)DMODEL * K3_2];

// ---------------- PTX helpers --------------------------------------------------
__device__ __forceinline__ uint32_t s2u(const void* p)
{
    uint32_t r;
    asm("{ .reg .u64 t; cvta.to.shared.u64 t, %1; cvt.u32.u64 %0, t; }"
        : "=r"(r) : "l"(p));
    return r;
}
__device__ __forceinline__ void cp16(uint32_t d, const void* s)
{
    asm volatile("cp.async.cg.shared.global [%0], [%1], 16;" :: "r"(d), "l"(s));
}
#define CP_COMMIT() asm volatile("cp.async.commit_group;" ::: "memory")
#define CP_WAIT1()  asm volatile("cp.async.wait_group 1;"  ::: "memory")

__device__ __forceinline__ void ldm4(uint32_t* r, uint32_t a)
{
    asm volatile("ldmatrix.sync.aligned.m8n8.x4.shared.b16 {%0,%1,%2,%3}, [%4];"
        : "=r"(r[0]), "=r"(r[1]), "=r"(r[2]), "=r"(r[3]) : "r"(a));
}
__device__ __forceinline__ void mma16816(float* d, const uint32_t* a, const uint32_t* b)
{
    asm volatile("mma.sync.aligned.m16n8k16.row.col.f32.bf16.bf16.f32 "
        "{%0,%1,%2,%3}, {%4,%5,%6,%7}, {%8,%9}, {%0,%1,%2,%3};"
        : "+f"(d[0]), "+f"(d[1]), "+f"(d[2]), "+f"(d[3])
        : "r"(a[0]), "r"(a[1]), "r"(a[2]), "r"(a[3]), "r"(b[0]), "r"(b[1]));
}
__device__ __forceinline__ float silu1(float v)
{
    return v / (1.f + expf(-v));
}
__device__ __forceinline__ uint32_t packbf2(float a, float b)
{
    __nv_bfloat162 t;
    t.x = __float2bfloat16(a);
    t.y = __float2bfloat16(b);
    return *(uint32_t*)&t;
}
// ---- packed f32x2 (Blackwell sm_100+) ----
__device__ __forceinline__ u64 pk2(float x, float y)
{
    u64 r;
    asm("mov.b64 %0, {%1, %2};" : "=l"(r) : "f"(x), "f"(y));
    return r;
}
__device__ __forceinline__ void upk2(float& x, float& y, u64 v)
{
    asm("mov.b64 {%0, %1}, %2;" : "=f"(x), "=f"(y) : "l"(v));
}
__device__ __forceinline__ u64 fma2_(u64 a, u64 b, u64 c)
{
    u64 d;
    asm("fma.rn.f32x2 %0, %1, %2, %3;" : "=l"(d) : "l"(a), "l"(b), "l"(c));
    return d;
}
__device__ __forceinline__ u64 mul2_(u64 a, u64 b)
{
    u64 d;
    asm("mul.rn.f32x2 %0, %1, %2;" : "=l"(d) : "l"(a), "l"(b));
    return d;
}
__device__ __forceinline__ u64 add2_(u64 a, u64 b)
{
    u64 d;
    asm("add.rn.f32x2 %0, %1, %2;" : "=l"(d) : "l"(a), "l"(b));
    return d;
}

// ---------------- theta = u @ theta_w  (blocked; tw cached in smem) -------------
#define THETA_SMEM ((32768 + 128 * 68) * 4)
__global__ void __launch_bounds__(256) k_theta(const float* __restrict__ u,
                                               const float* __restrict__ tw)
{
    extern __shared__ float ts[];
    float* stw = ts;            // 32768 floats
    float* su  = ts + 32768;    // 128 x 68 (pad 4)
    int m0 = blockIdx.x * 128, tid = threadIdx.x;
    #pragma unroll
    for (int i = 0; i < 32; ++i) {
        int idx = tid + i * 256;
        *(float4*)(stw + idx * 4) = *(const float4*)(tw + idx * 4);
    }
    int row = tid >> 1, cb = (tid & 1) * 16;
    float acc[16];
    #pragma unroll
    for (int c = 0; c < 16; ++c) acc[c] = 0.f;

    for (int kc = 0; kc < 16; ++kc) {
        __syncthreads();
        #pragma unroll
        for (int j = 0; j < 8; ++j) {
            int idx4 = tid + j * 256;
            int rw = idx4 >> 4, cc = (idx4 & 15) * 4;
            *(float4*)(su + rw * 68 + cc) =
                *(const float4*)(u + (size_t)(m0 + rw) * 1024 + kc * 64 + cc);
        }
        __syncthreads();
        #pragma unroll 8
        for (int kk = 0; kk < 64; ++kk) {
            float xv = su[row * 68 + kk];
            const float* twp = stw + (kc * 64 + kk) * 32 + cb;
            float4 w0 = *(const float4*)(twp);
            float4 w1 = *(const float4*)(twp + 4);
            float4 w2 = *(const float4*)(twp + 8);
            float4 w3 = *(const float4*)(twp + 12);
            acc[0]  = fmaf(xv, w0.x, acc[0]);  acc[1]  = fmaf(xv, w0.y, acc[1]);
            acc[2]  = fmaf(xv, w0.z, acc[2]);  acc[3]  = fmaf(xv, w0.w, acc[3]);
            acc[4]  = fmaf(xv, w1.x, acc[4]);  acc[5]  = fmaf(xv, w1.y, acc[5]);
            acc[6]  = fmaf(xv, w1.z, acc[6]);  acc[7]  = fmaf(xv, w1.w, acc[7]);
            acc[8]  = fmaf(xv, w2.x, acc[8]);  acc[9]  = fmaf(xv, w2.y, acc[9]);
            acc[10] = fmaf(xv, w2.z, acc[10]); acc[11] = fmaf(xv, w2.w, acc[11]);
            acc[12] = fmaf(xv, w3.x, acc[12]); acc[13] = fmaf(xv, w3.y, acc[13]);
            acc[14] = fmaf(xv, w3.z, acc[14]); acc[15] = fmaf(xv, w3.w, acc[15]);
        }
    }
    float* out = g_theta + (size_t)(m0 + row) * 32 + cb;
    #pragma unroll
    for (int c = 0; c < 16; c += 4) {
        float4 v = {acc[c], acc[c+1], acc[c+2], acc[c+3]};
        *(float4*)(out + c) = v;
    }
}

// ---------------- layernorm + K3 hi/lo pack -------------------------------------
__global__ void __launch_bounds__(256) k_ln(const float* __restrict__ u,
        const float* __restrict__ gscale, const float* __restrict__ gbias)
{
    __shared__ float rsum[8], rsq[8];
    __shared__ float s_mu, s_rs;
    int m = blockIdx.x, tid = threadIdx.x;
    const float* ur = u + (size_t)m * 1024 + tid * 4;
    float4 v = *(const float4*)ur;
    float s = v.x + v.y + v.z + v.w;
    float q = v.x*v.x + v.y*v.y + v.z*v.z + v.w*v.w;
    #pragma unroll
    for (int o = 16; o; o >>= 1) {
        s += __shfl_xor_sync(0xffffffffu, s, o);
        q += __shfl_xor_sync(0xffffffffu, q, o);
    }
    int lane = tid & 31, wid = tid >> 5;
    if (lane == 0) { rsum[wid] = s; rsq[wid] = q; }
    __syncthreads();
    if (tid == 0) {
        float S = 0.f, Q = 0.f;
        #pragma unroll
        for (int i = 0; i < 8; i++) { S += rsum[i]; Q += rsq[i]; }
        float mu  = S * (1.f / 1024.f);
        float var = Q * (1.f / 1024.f) - mu * mu;
        s_mu = mu;
        s_rs = rsqrtf(var + 1e-6f);
    }
    __syncthreads();
    float mu = s_mu, rs = s_rs;
    float4 sc = *(const float4*)(gscale + tid * 4);
    float4 bi = *(const float4*)(gbias  + tid * 4);
    float o0 = (v.x - mu) * rs * sc.x + bi.x;
    float o1 = (v.y - mu) * rs * sc.y + bi.y;
    float o2 = (v.z - mu) * rs * sc.z + bi.z;
    float o3 = (v.w - mu) * rs * sc.w + bi.w;
    uint32_t h01 = packbf2(o0, o1);
    uint32_t h23 = packbf2(o2, o3);
    __nv_bfloat162 hv01 = *(__nv_bfloat162*)&h01;
    __nv_bfloat162 hv23 = *(__nv_bfloat162*)&h23;
    uint32_t l01 = packbf2(o0 - __bfloat162float(hv01.x),
                           o1 - __bfloat162float(hv01.y));
    uint32_t l23 = packbf2(o2 - __bfloat162float(hv23.x),
                           o3 - __bfloat162float(hv23.y));
    __nv_bfloat16* row = g_a3 + (size_t)m * K3_1;
    uint2 H = {h01, h23}, L = {l01, l23};
    *(uint2*)(row + tid * 4)        = H;
    *(uint2*)(row + 1024 + tid * 4) = L;
    *(uint2*)(row + 2048 + tid * 4) = H;
}

// ---------------- weight transpose + K3 split: T[n][3K] = [hi, hi, lo] ---------
__global__ void k_tsplit(const float* __restrict__ W, int K, int N,
                         __nv_bfloat16* __restrict__ T)
{
    __shared__ float t[32][33];
    int nb = blockIdx.x * 32, kb = blockIdx.y * 32;
    int x = threadIdx.x, y = threadIdx.y;   // 32 x 8
    #pragma unroll
    for (int i = 0; i < 32; i += 8) {
        int k = kb + y + i, n = nb + x;
        t[y + i][x] = (n < N) ? W[(size_t)k * N + n] : 0.f;
    }
    __syncthreads();
    #pragma unroll
    for (int i = 0; i < 32; i += 8) {
        int n = nb + y + i, k = kb + x;
        float v = t[x][y + i];
        __nv_bfloat16 h = __float2bfloat16(v);
        __nv_bfloat16 l = __float2bfloat16(v - __bfloat162float(h));
        __nv_bfloat16* row = T + (size_t)n * 3 * K;
        row[k]         = h;
        row[K + k]     = h;
        row[2 * K + k] = l;
    }
}

// ---------------- mma.sync bf16 GEMM (K3, 128x128 CTA, 64x64 warp, BK=64) -------
// 128 threads = 4 warps (2m x 2n), warp tile 64x64, 3-stage cp.async.
// MODE 0: fused proj epilogue; MODE 1: C = result + ADD
#define GSTAGE 32768
#define GSMEM  (3 * GSTAGE)

template<int MODE>
__global__ void __launch_bounds__(128, 2)
k_gemm_mma(const __nv_bfloat16* __restrict__ A, const __nv_bfloat16* __restrict__ B,
           const float* __restrict__ ADD, float* __restrict__ C, int N, int Kp)
{
    extern __shared__ char sm[];
    uint32_t smu = s2u(sm);
    int tid = threadIdx.x, wid = tid >> 5, lane = tid & 31;
    int n0 = blockIdx.x * 128, m0 = blockIdx.y * 128;
    int KT = Kp >> 6;

    auto issue = [&](int kt, int slot) {
        uint32_t st = smu + slot * GSTAGE;
        size_t k0 = (size_t)kt * 64;
        #pragma unroll
        for (int t = 0; t < 8; ++t) {
            int idx = tid + t * 128;
            int rw = idx >> 3, c = idx & 7;
            uint32_t sw = (uint32_t)(rw * 128) + (uint32_t)((c ^ (rw & 7)) << 4);
            cp16(st + sw, A + (size_t)(m0 + rw) * Kp + k0 + c * 8);
        }
        #pragma unroll
        for (int t = 0; t < 8; ++t) {
            int idx = tid + t * 128;
            int rw = idx >> 3, c = idx & 7;
            uint32_t sw = (uint32_t)(rw * 128) + (uint32_t)((c ^ (rw & 7)) << 4);
            cp16(st + 16384 + sw, B + (size_t)(n0 + rw) * Kp + k0 + c * 8);
        }
    };

    issue(0, 0); CP_COMMIT();
    issue(1, 1); CP_COMMIT();

    float d[4][8][4];
    #pragma unroll
    for (int i = 0; i < 4; i++)
        #pragma unroll
        for (int j = 0; j < 8; j++)
            #pragma unroll
            for (int e = 0; e < 4; e++) d[i][j][e] = 0.f;

    int mo = (wid >> 1) * 64, no = (wid & 1) * 64;

    for (int kt = 0; kt < KT; ++kt) {
        CP_WAIT1();
        __syncthreads();
        if (kt + 2 < KT) issue(kt + 2, (kt + 2) % 3);
        CP_COMMIT();

        uint32_t sA = smu + (kt % 3) * GSTAGE;
        uint32_t sB = sA + 16384;
        #pragma unroll
        for (int ks = 0; ks < 4; ++ks) {
            uint32_t afr[4][4], bfr[4][4];
            {
                int c = ks * 2 + (lane >> 4);
                #pragma unroll
                for (int ma = 0; ma < 4; ++ma) {
                    int r = mo + ma * 16 + (lane & 15);
                    ldm4(afr[ma], sA + (uint32_t)(r * 128) + (uint32_t)((c ^ (r & 7)) << 4));
                }
            }
            {
                int c = ks * 2 + ((lane >> 3) & 1);
                #pragma unroll
                for (int nb = 0; nb < 4; ++nb) {
                    int r = no + nb * 16 + (lane & 7) + (((lane >> 4) & 1) << 3);
                    ldm4(bfr[nb], sB + (uint32_t)(r * 128) + (uint32_t)((c ^ (r & 7)) << 4));
                }
            }
            #pragma unroll
            for (int mi = 0; mi < 4; ++mi)
                #pragma unroll
                for (int ni = 0; ni < 8; ++ni)
                    mma16816(d[mi][ni], afr[mi], &bfr[ni >> 1][(ni & 1) * 2]);
        }
    }

    // epilogue
    #pragma unroll
    for (int mi = 0; mi < 4; ++mi) {
        int r0 = m0 + mo + mi * 16 + (lane >> 2);
        #pragma unroll
        for (int ni = 0; ni < 8; ++ni) {
            int col = n0 + no + ni * 8 + (lane & 3) * 2;
            #pragma unroll
            for (int half = 0; half < 2; ++half) {
                int row = r0 + half * 8;
                float2 v = {d[mi][ni][half * 2], d[mi][ni][half * 2 + 1]};
                if (MODE == 0) {
                    if (col < 2048) {
                        float2 o = {silu1(v.x), silu1(v.y)};
                        *(float2*)(g_xs + (size_t)row * 2048 + col) = o;
                    } else if (col < 4096) {
                        float2 o = {silu1(v.x), silu1(v.y)};
                        *(float2*)(g_sz + (size_t)row * 2048 + col - 2048) = o;
                    } else if (col < 4256) {
                        *(float2*)(g_tail + (size_t)row * 160 + col - 4096) = v;
                    }
                } else {
                    if (col < N) {
                        float2 a2 = *(const float2*)(ADD + (size_t)row * N + col);
                        v.x += a2.x; v.y += a2.y;
                        *(float2*)(C + (size_t)row * N + col) = v;
                    }
                }
            }
        }
    }
}

// ---------------- per-row prep (tail only) --------------------------------------
__global__ void __launch_bounds__(96) k_prep(const float* __restrict__ A_log,
        const float* __restrict__ dt_bias,
        const float* __restrict__ bcB, const float* __restrict__ bcC,
        const float* __restrict__ Bbias, const float* __restrict__ Cbias)
{
    int m = blockIdx.x, tid = threadIdx.x;
    const float* tail = g_tail + (size_t)m * 160;
    __shared__ float s_dts;

    int lane = tid & 31, wid = tid >> 5;
    if (wid == 0) {
        float b0 = tail[lane], b1 = tail[32 + lane];
        float ss = b0 * b0 + b1 * b1;
        #pragma unroll
        for (int o = 16; o; o >>= 1) ss += __shfl_xor_sync(0xffffffffu, ss, o);
        float r = rsqrtf(ss * (1.f / 64.f) + 1e-6f);
        g_Bc[(size_t)m * 64 + lane]      = b0 * r * bcB[lane]      + Bbias[lane];
        g_Bc[(size_t)m * 64 + 32 + lane] = b1 * r * bcB[32 + lane] + Bbias[32 + lane];
    } else if (wid == 1) {
        float b0 = tail[64 + lane], b1 = tail[96 + lane];
        float ss = b0 * b0 + b1 * b1;
        #pragma unroll
        for (int o = 16; o; o >>= 1) ss += __shfl_xor_sync(0xffffffffu, ss, o);
        float r = rsqrtf(ss * (1.f / 64.f) + 1e-6f);
        g_Cc[(size_t)m * 64 + lane]      = b0 * r * bcC[lane]      + Cbias[lane];
        g_Cc[(size_t)m * 64 + 32 + lane] = b1 * r * bcC[32 + lane] + Cbias[32 + lane];
    } else {
        float dt = 0.f;
        if (lane < 16) {
            float x = tail[128 + lane] + dt_bias[lane];
            dt = (x > 20.f) ? x : log1pf(expf(x));
            float lamr = tail[144 + lane];
            float lam = 1.f / (1.f + expf(-lamr));
            float a = expf(-expf(A_log[lane]) * dt);
            size_t o = ((size_t)m * 16 + lane) * 4;
            g_coef[o]     = a;
            g_coef[o + 1] = dt * lam;
            g_coef[o + 2] = dt * (1.f - lam) * a;
            g_coef[o + 3] = 0.f;
        }
        float s = dt;
        #pragma unroll
        for (int o = 16; o; o >>= 1) s += __shfl_xor_sync(0xffffffffu, s, o);
        if (lane == 0) s_dts = s * (1.f / 16.f);
    }
    __syncthreads();
    if (tid < 32)
        g_phi[(size_t)m * 32 + tid] = s_dts * g_theta[(size_t)m * 32 + tid];
}

// ---------------- 3-phase cumsum (phase 3 fused with RoPE) ----------------------
__global__ void k_cs_chunk()
{
    int b = blockIdx.x >> 6, ch = blockIdx.x & 63;
    int c = threadIdx.x;
    size_t base = (((size_t)b * 4096) + (size_t)ch * 64) * 32 + c;
    float acc = 0.f;
    #pragma unroll 8
    for (int l = 0; l < 64; ++l) {
        acc += g_phi[base + (size_t)l * 32];
        g_phi[base + (size_t)l * 32] = acc;
    }
    g_csum[((size_t)(b * 64 + ch)) * 32 + c] = acc;
}
__global__ void k_cs_scan()
{
    int tid = threadIdx.x;
    int b = tid >> 5, c = tid & 31;
    float acc = 0.f;
    #pragma unroll 8
    for (int ch = 0; ch < 64; ++ch) {
        size_t o = ((size_t)(b * 64 + ch)) * 32 + c;
        float t = g_csum[o];
        g_csum[o] = acc;
        acc += t;
    }
}
__global__ void k_cs_add_rope()
{
    int b = blockIdx.x >> 6, ch = blockIdx.x & 63;
    __shared__ float off[32];
    if (threadIdx.x < 32)
        off[threadIdx.x] = g_csum[((size_t)(b * 64 + ch)) * 32 + threadIdx.x];
    __syncthreads();
    size_t mbase = (size_t)b * 4096 + (size_t)ch * 64;
    for (int e = threadIdx.x; e < 2048; e += 256) {
        int r = e >> 5, c = e & 31;
        size_t m = mbase + r;
        float ph = g_phi[m * 32 + c] + off[c];
        float cc = cosf(ph), ss = sinf(ph);
        size_t o = m * 64 + c;
        float xr = g_Bc[o], xi = g_Bc[o + 32];
        g_Bc[o]      = xr * cc - xi * ss;
        g_Bc[o + 32] = xr * ss + xi * cc;
        xr = g_Cc[o]; xi = g_Cc[o + 32];
        g_Cc[o]      = xr * cc - xi * ss;
        g_Cc[o + 32] = xr * ss + xi * cc;
    }
}

// ---------------- SSD scan + gate + bf16 K3 pack (4p x 8n, s-substitution) ------
// grid 128 = (b:4, h:16, pg2:2); 128 threads: pq = tid>>3 (16), nsub = tid&7.
#define SCHUNK 32
#define ST2_F  8320
#define SCAN_SMEM ((2 * ST2_F + 2048) * 4)   // 74752 bytes

__global__ void __launch_bounds__(128) k_scan(const float* __restrict__ Dv)
{
    extern __shared__ float sf[];
    uint32_t smu = s2u(sf);
    int bx = blockIdx.x;
    int pg2 = bx & 1, h = (bx >> 1) & 15, b = bx >> 5;
    int tid = threadIdx.x;
    int nsub = tid & 7, pq = tid >> 3;
    size_t mb = (size_t)b * 4096;
    const float* Bg = g_Bc + mb * 64;
    const float* Cg = g_Cc + mb * 64;
    const float* Xg = g_xs + mb * 2048 + h * 128 + pg2 * 64;
    const float* Zg = g_sz + mb * 2048 + h * 128 + pg2 * 64;
    const float* Kg = g_coef + (mb * 16 + h) * 4;
    float Dh = Dv[h];
    int jbase = h * 128 + pg2 * 64;

    auto load_chunk = [&](int c, int slot) {
        int t0 = c * SCHUNK;
        uint32_t sb = smu + slot * ST2_F * 4;
        #pragma unroll
        for (int i = 0; i < 4; ++i) {
            int idx = tid + i * 128;
            int t = idx >> 4, seg = idx & 15;
            cp16(sb + (uint32_t)(t * 64 + seg * 4) * 4,
                 Bg + (size_t)(t0 + t) * 64 + seg * 4);
        }
        #pragma unroll
        for (int i = 0; i < 4; ++i) {
            int idx = tid + i * 128;
            int t = idx >> 4, seg = idx & 15;
            cp16(sb + (uint32_t)(2048 + t * 64 + seg * 4) * 4,
                 Cg + (size_t)(t0 + t) * 64 + seg * 4);
        }
        #pragma unroll
        for (int i = 0; i < 4; ++i) {
            int idx = tid + i * 128;
            int t = idx >> 4, seg = idx & 15;
            cp16(sb + (uint32_t)(4096 + t * 64 + seg * 4) * 4,
                 Xg + (size_t)(t0 + t) * 2048 + seg * 4);
        }
        #pragma unroll
        for (int i = 0; i < 4; ++i) {
            int idx = tid + i * 128;
            int t = idx >> 4, seg = idx & 15;
            cp16(sb + (uint32_t)(6144 + t * 64 + seg * 4) * 4,
                 Zg + (size_t)(t0 + t) * 2048 + seg * 4);
        }
        if (tid < SCHUNK)
            cp16(sb + (uint32_t)(8192 + tid * 4) * 4,
                 Kg + (size_t)(t0 + tid) * 64);
    };

    u64 s2[4][4], Bp2[4];
    #pragma unroll
    for (int p = 0; p < 4; ++p)
        #pragma unroll
        for (int i = 0; i < 4; ++i) s2[p][i] = 0ull;
    #pragma unroll
    for (int i = 0; i < 4; ++i) Bp2[i] = 0ull;
    float4 xprev = {0.f, 0.f, 0.f, 0.f};
    float alpha_prev = 0.f;
    float* ybuf = sf + 2 * ST2_F;

    load_chunk(0, 0); CP_COMMIT();
    load_chunk(1, 1); CP_COMMIT();

    const int NCHUNK = LL / SCHUNK;   // 128
    for (int c = 0; c < NCHUNK; ++c) {
        int slot = c & 1;
        const float* st = sf + slot * ST2_F;
        CP_WAIT1();
        __syncthreads();
        #pragma unroll 2
        for (int t = 0; t < SCHUNK; ++t) {
            ulonglong2 B01 = *(const ulonglong2*)(st + t * 64 + nsub * 8);
            ulonglong2 B23 = *(const ulonglong2*)(st + t * 64 + nsub * 8 + 4);
            ulonglong2 C01 = *(const ulonglong2*)(st + 2048 + t * 64 + nsub * 8);
            ulonglong2 C23 = *(const ulonglong2*)(st + 2048 + t * 64 + nsub * 8 + 4);
            float4 cf = *(const float4*)(st + 8192 + t * 4);
            float4 x4 = *(const float4*)(st + 4096 + t * 64 + pq * 4);
            u64 Bn[4] = {B01.x, B01.y, B23.x, B23.y};
            u64 Cn[4] = {C01.x, C01.y, C23.x, C23.y};

            float delta = fmaf(cf.x, alpha_prev, cf.z);
            u64 ca2 = pk2(cf.x, cf.x);
            u64 e2[4];
            e2[0] = pk2(delta * xprev.x, delta * xprev.x);
            e2[1] = pk2(delta * xprev.y, delta * xprev.y);
            e2[2] = pk2(delta * xprev.z, delta * xprev.z);
            e2[3] = pk2(delta * xprev.w, delta * xprev.w);

            u64 cb2 = 0ull;
            u64 acc2[4] = {0ull, 0ull, 0ull, 0ull};
            #pragma unroll
            for (int i = 0; i < 4; ++i) {
                cb2 = fma2_(Bn[i], Cn[i], cb2);
                #pragma unroll
                for (int p = 0; p < 4; ++p) {
                    s2[p][i] = fma2_(ca2, s2[p][i], mul2_(e2[p], Bp2[i]));
                    acc2[p] = fma2_(s2[p][i], Cn[i], acc2[p]);
                }
                Bp2[i] = Bn[i];
            }
            float a0l, a0h, a1l, a1h, a2l, a2h, a3l, a3h, cbl, cbh;
            upk2(a0l, a0h, acc2[0]); upk2(a1l, a1h, acc2[1]);
            upk2(a2l, a2h, acc2[2]); upk2(a3l, a3h, acc2[3]);
            upk2(cbl, cbh, cb2);
            u64 q01 = pk2(a0l + a0h, a1l + a1h);
            u64 q23 = pk2(a2l + a2h, a3l + a3h);
            float cb = cbl + cbh;
            #pragma unroll
            for (int o = 1; o < 8; o <<= 1) {
                q01 = add2_(q01, __shfl_xor_sync(0xffffffffu, q01, o));
                q23 = add2_(q23, __shfl_xor_sync(0xffffffffu, q23, o));
                cb += __shfl_xor_sync(0xffffffffu, cb, o);
            }
            if (nsub == 0) {
                float y0, y1, y2, y3;
                upk2(y0, y1, q01);
                upk2(y2, y3, q23);
                float axcb = cf.y * cb;
                float4 z4 = *(const float4*)(st + 6144 + t * 64 + pq * 4);
                float4 yo;
                yo.x = (y0 + x4.x * (axcb + Dh)) * z4.x;
                yo.y = (y1 + x4.y * (axcb + Dh)) * z4.y;
                yo.z = (y2 + x4.z * (axcb + Dh)) * z4.z;
                yo.w = (y3 + x4.w * (axcb + Dh)) * z4.w;
                *(float4*)(ybuf + t * 64 + pq * 4) = yo;
            }
            xprev = x4;
            alpha_prev = cf.y;
        }
        __syncthreads();
        #pragma unroll
        for (int i = 0; i < 4; ++i) {
            int idx = tid + i * 128;
            int t = idx >> 4, p0 = (idx & 15) * 4;
            float4 y4 = *(const float4*)(ybuf + t * 64 + p0);
            uint32_t h01 = packbf2(y4.x, y4.y);
            uint32_t h23 = packbf2(y4.z, y4.w);
            __nv_bfloat162 hv01 = *(__nv_bfloat162*)&h01;
            __nv_bfloat162 hv23 = *(__nv_bfloat162*)&h23;
            uint32_t l01 = packbf2(y4.x - __bfloat162float(hv01.x),
                                   y4.y - __bfloat162float(hv01.y));
            uint32_t l23 = packbf2(y4.z - __bfloat162float(hv23.x),
                                   y4.w - __bfloat162float(hv23.y));
            size_t row = mb + (size_t)c * SCHUNK + t;
            __nv_bfloat16* rp = g_yz3 + row * K3_2 + jbase + p0;
            uint2 H = {h01, h23}, L = {l01, l23};
            *(uint2*)rp          = H;
            *(uint2*)(rp + 2048) = L;
            *(uint2*)(rp + 4096) = H;
        }
        if (c + 2 < NCHUNK) load_chunk(c + 2, slot);
        CP_COMMIT();
    }
}

// ---------------- host launcher --------------------------------------------------
template<typename T>
static T* sym_addr(const void* s)
{
    void* p = nullptr;
    cudaGetSymbolAddress(&p, s);
    return (T*)p;
}

extern "C" void kernel_launch(void* const* d_in, const int* in_sizes, int n_in,
                              void* d_out, int out_size)
{
    const float* u          = (const float*)d_in[0];
    const float* norm_scale = (const float*)d_in[1];
    const float* norm_bias  = (const float*)d_in[2];
    const float* in_proj_w  = (const float*)d_in[3];
    const float* A_log      = (const float*)d_in[4];
    const float* dt_bias    = (const float*)d_in[5];
    const float* bcB_scale  = (const float*)d_in[6];
    const float* bcC_scale  = (const float*)d_in[7];
    const float* B_bias     = (const float*)d_in[8];
    const float* C_bias     = (const float*)d_in[9];
    const float* theta_w    = (const float*)d_in[10];
    const float* Dv         = (const float*)d_in[11];
    const float* out_proj_w = (const float*)d_in[12];
    float* out = (float*)d_out;

    __nv_bfloat16* p_a3  = sym_addr<__nv_bfloat16>(g_a3);
    __nv_bfloat16* p_yz3 = sym_addr<__nv_bfloat16>(g_yz3);
    __nv_bfloat16* p_w31 = sym_addr<__nv_bfloat16>(g_w31);
    __nv_bfloat16* p_w32 = sym_addr<__nv_bfloat16>(g_w32);

    static bool attr_done = false;
    if (!attr_done) {
        cudaFuncSetAttribute(k_gemm_mma<0>,
            cudaFuncAttributeMaxDynamicSharedMemorySize, GSMEM);
        cudaFuncSetAttribute(k_gemm_mma<1>,
            cudaFuncAttributeMaxDynamicSharedMemorySize, GSMEM);
        cudaFuncSetAttribute(k_scan,
            cudaFuncAttributeMaxDynamicSharedMemorySize, SCAN_SMEM);
        cudaFuncSetAttribute(k_theta,
            cudaFuncAttributeMaxDynamicSharedMemorySize, THETA_SMEM);
        attr_done = true;
    }

    // 1. theta = u @ theta_w (blocked, tw cached in smem)
    k_theta<<<MROWS / 128, 256, THETA_SMEM>>>(u, theta_w);
    // 2. layernorm + K3 hi/lo pack
    k_ln<<<MROWS, 256>>>(u, norm_scale, norm_bias);
    // 3. weight transpose + K3 pack
    k_tsplit<<<dim3(NPAD1 / 32, DMODEL / 32), dim3(32, 8)>>>(
        in_proj_w, DMODEL, PROJ, p_w31);
    k_tsplit<<<dim3(DMODEL / 32, DINNER / 32), dim3(32, 8)>>>(
        out_proj_w, DINNER, DMODEL, p_w32);
    // 4. proj GEMM (K3, 128x128 CTA / 64x64 warp, fused epilogue)
    k_gemm_mma<0><<<dim3(NPAD1 / 128, MROWS / 128), 128, GSMEM>>>(
        p_a3, p_w31, nullptr, nullptr, PROJ, K3_1);
    // 5. tail prep
    k_prep<<<MROWS, 96>>>(A_log, dt_bias, bcB_scale, bcC_scale, B_bias, C_bias);
    // 6. cumsum(phi) + fused RoPE
    k_cs_chunk<<<BB * 64, 32>>>();
    k_cs_scan<<<1, 128>>>();
    k_cs_add_rope<<<BB * 64, 256>>>();
    // 7. SSD scan + gate + pack (4p x 8n; 128 blocks)
    k_scan<<<BB * NHEADS * 2, 128, SCAN_SMEM>>>(Dv);
    // 8. out = yz @ out_proj_w + u (K3, 128x128 CTA / 64x64 warp)
    k_gemm_mma<1><<<dim3(DMODEL / 128, MROWS / 128), 128, GSMEM>>>(
        p_yz3, p_w32, u, out, DMODEL, K3_2);
}

// round 17
// speedup vs baseline: 1.2599x; 1.2191x over previous
#include <cuda_runtime.h>
#include <cuda_bf16.h>
#include <cuda_fp16.h>
#include <math.h>
#include <stdint.h>

// ---------------- problem constants ----------------
#define BB      4
#define LL      4096
#define DMODEL  1024
#define DINNER  2048
#define NHEADS  16
#define DSTATE  64
#define PROJ    4256
#define MROWS   (BB*LL)          // 16384
#define NPAD1   4352             // 34 * 128
#define K3_1    (3*DMODEL)       // 3072
#define K3_2    (3*DINNER)       // 6144

typedef unsigned long long u64;

// ---------------- scratch (__device__ globals; no runtime alloc) -------------
__device__ __align__(16) float g_xs   [(size_t)MROWS * DINNER];   // silu(x)
__device__ __align__(16) float g_sz   [(size_t)MROWS * DINNER];   // silu(z)
__device__ __align__(16) float g_tail [(size_t)MROWS * 160];      // B,C,dt,lam raw
__device__ __align__(16) float g_Bc   [(size_t)MROWS * DSTATE];
__device__ __align__(16) float g_Cc   [(size_t)MROWS * DSTATE];
__device__ __align__(16) float g_coef [(size_t)MROWS * NHEADS * 4];
__device__ __align__(16) float g_theta[(size_t)MROWS * 32];
__device__ __align__(16) float g_phi  [(size_t)MROWS * 32];
__device__ __align__(16) float g_csum [(size_t)BB * 64 * 32];
// fp16 split operands: A = [hi, lo, hi] (prefix 2/3 = exact value),
//                      W = [hi, hi, lo] (prefix 2/3 = [wh, wh])
__device__ __align__(16) __half g_a3f [(size_t)MROWS * K3_1];
__device__ __align__(16) __half g_yz3f[(size_t)MROWS * K3_2];
__device__ __align__(16) __half g_w1f [(size_t)NPAD1 * K3_1];
__device__ __align__(16) __half g_w2f [(size_t)DMODEL * K3_2];

// ---------------- PTX helpers --------------------------------------------------
__device__ __forceinline__ uint32_t s2u(const void* p)
{
    uint32_t r;
    asm("{ .reg .u64 t; cvta.to.shared.u64 t, %1; cvt.u32.u64 %0, t; }"
        : "=r"(r) : "l"(p));
    return r;
}
__device__ __forceinline__ void cp16(uint32_t d, const void* s)
{
    asm volatile("cp.async.cg.shared.global [%0], [%1], 16;" :: "r"(d), "l"(s));
}
#define CP_COMMIT() asm volatile("cp.async.commit_group;" ::: "memory")
#define CP_WAIT1()  asm volatile("cp.async.wait_group 1;"  ::: "memory")

__device__ __forceinline__ void ldm4(uint32_t* r, uint32_t a)
{
    asm volatile("ldmatrix.sync.aligned.m8n8.x4.shared.b16 {%0,%1,%2,%3}, [%4];"
        : "=r"(r[0]), "=r"(r[1]), "=r"(r[2]), "=r"(r[3]) : "r"(a));
}
__device__ __forceinline__ void mma16816h(float* d, const uint32_t* a, const uint32_t* b)
{
    asm volatile("mma.sync.aligned.m16n8k16.row.col.f32.f16.f16.f32 "
        "{%0,%1,%2,%3}, {%4,%5,%6,%7}, {%8,%9}, {%0,%1,%2,%3};"
        : "+f"(d[0]), "+f"(d[1]), "+f"(d[2]), "+f"(d[3])
        : "r"(a[0]), "r"(a[1]), "r"(a[2]), "r"(a[3]), "r"(b[0]), "r"(b[1]));
}
__device__ __forceinline__ float silu1(float v)
{
    return v / (1.f + expf(-v));
}
__device__ __forceinline__ uint32_t packhf2(float a, float b)
{
    __half2 t = __floats2half2_rn(a, b);
    return *(uint32_t*)&t;
}
// ---- packed f32x2 (Blackwell sm_100+) ----
__device__ __forceinline__ u64 pk2(float x, float y)
{
    u64 r;
    asm("mov.b64 %0, {%1, %2};" : "=l"(r) : "f"(x), "f"(y));
    return r;
}
__device__ __forceinline__ void upk2(float& x, float& y, u64 v)
{
    asm("mov.b64 {%0, %1}, %2;" : "=f"(x), "=f"(y) : "l"(v));
}
__device__ __forceinline__ u64 fma2_(u64 a, u64 b, u64 c)
{
    u64 d;
    asm("fma.rn.f32x2 %0, %1, %2, %3;" : "=l"(d) : "l"(a), "l"(b), "l"(c));
    return d;
}
__device__ __forceinline__ u64 mul2_(u64 a, u64 b)
{
    u64 d;
    asm("mul.rn.f32x2 %0, %1, %2;" : "=l"(d) : "l"(a), "l"(b));
    return d;
}
__device__ __forceinline__ u64 add2_(u64 a, u64 b)
{
    u64 d;
    asm("add.rn.f32x2 %0, %1, %2;" : "=l"(d) : "l"(a), "l"(b));
    return d;
}

// ---------------- theta = u @ theta_w  (blocked; tw cached in smem) -------------
#define THETA_SMEM ((32768 + 128 * 68) * 4)
__global__ void __launch_bounds__(256) k_theta(const float* __restrict__ u,
                                               const float* __restrict__ tw)
{
    extern __shared__ float ts[];
    float* stw = ts;            // 32768 floats
    float* su  = ts + 32768;    // 128 x 68 (pad 4)
    int m0 = blockIdx.x * 128, tid = threadIdx.x;
    #pragma unroll
    for (int i = 0; i < 32; ++i) {
        int idx = tid + i * 256;
        *(float4*)(stw + idx * 4) = *(const float4*)(tw + idx * 4);
    }
    int row = tid >> 1, cb = (tid & 1) * 16;
    float acc[16];
    #pragma unroll
    for (int c = 0; c < 16; ++c) acc[c] = 0.f;

    for (int kc = 0; kc < 16; ++kc) {
        __syncthreads();
        #pragma unroll
        for (int j = 0; j < 8; ++j) {
            int idx4 = tid + j * 256;
            int rw = idx4 >> 4, cc = (idx4 & 15) * 4;
            *(float4*)(su + rw * 68 + cc) =
                *(const float4*)(u + (size_t)(m0 + rw) * 1024 + kc * 64 + cc);
        }
        __syncthreads();
        #pragma unroll 8
        for (int kk = 0; kk < 64; ++kk) {
            float xv = su[row * 68 + kk];
            const float* twp = stw + (kc * 64 + kk) * 32 + cb;
            float4 w0 = *(const float4*)(twp);
            float4 w1 = *(const float4*)(twp + 4);
            float4 w2 = *(const float4*)(twp + 8);
            float4 w3 = *(const float4*)(twp + 12);
            acc[0]  = fmaf(xv, w0.x, acc[0]);  acc[1]  = fmaf(xv, w0.y, acc[1]);
            acc[2]  = fmaf(xv, w0.z, acc[2]);  acc[3]  = fmaf(xv, w0.w, acc[3]);
            acc[4]  = fmaf(xv, w1.x, acc[4]);  acc[5]  = fmaf(xv, w1.y, acc[5]);
            acc[6]  = fmaf(xv, w1.z, acc[6]);  acc[7]  = fmaf(xv, w1.w, acc[7]);
            acc[8]  = fmaf(xv, w2.x, acc[8]);  acc[9]  = fmaf(xv, w2.y, acc[9]);
            acc[10] = fmaf(xv, w2.z, acc[10]); acc[11] = fmaf(xv, w2.w, acc[11]);
            acc[12] = fmaf(xv, w3.x, acc[12]); acc[13] = fmaf(xv, w3.y, acc[13]);
            acc[14] = fmaf(xv, w3.z, acc[14]); acc[15] = fmaf(xv, w3.w, acc[15]);
        }
    }
    float* out = g_theta + (size_t)(m0 + row) * 32 + cb;
    #pragma unroll
    for (int c = 0; c < 16; c += 4) {
        float4 v = {acc[c], acc[c+1], acc[c+2], acc[c+3]};
        *(float4*)(out + c) = v;
    }
}

// ---------------- layernorm + fp16 [hi, lo, hi] pack -----------------------------
__global__ void __launch_bounds__(256) k_ln(const float* __restrict__ u,
        const float* __restrict__ gscale, const float* __restrict__ gbias)
{
    __shared__ float rsum[8], rsq[8];
    __shared__ float s_mu, s_rs;
    int m = blockIdx.x, tid = threadIdx.x;
    const float* ur = u + (size_t)m * 1024 + tid * 4;
    float4 v = *(const float4*)ur;
    float s = v.x + v.y + v.z + v.w;
    float q = v.x*v.x + v.y*v.y + v.z*v.z + v.w*v.w;
    #pragma unroll
    for (int o = 16; o; o >>= 1) {
        s += __shfl_xor_sync(0xffffffffu, s, o);
        q += __shfl_xor_sync(0xffffffffu, q, o);
    }
    int lane = tid & 31, wid = tid >> 5;
    if (lane == 0) { rsum[wid] = s; rsq[wid] = q; }
    __syncthreads();
    if (tid == 0) {
        float S = 0.f, Q = 0.f;
        #pragma unroll
        for (int i = 0; i < 8; i++) { S += rsum[i]; Q += rsq[i]; }
        float mu  = S * (1.f / 1024.f);
        float var = Q * (1.f / 1024.f) - mu * mu;
        s_mu = mu;
        s_rs = rsqrtf(var + 1e-6f);
    }
    __syncthreads();
    float mu = s_mu, rs = s_rs;
    float4 sc = *(const float4*)(gscale + tid * 4);
    float4 bi = *(const float4*)(gbias  + tid * 4);
    float o0 = (v.x - mu) * rs * sc.x + bi.x;
    float o1 = (v.y - mu) * rs * sc.y + bi.y;
    float o2 = (v.z - mu) * rs * sc.z + bi.z;
    float o3 = (v.w - mu) * rs * sc.w + bi.w;
    uint32_t h01 = packhf2(o0, o1);
    uint32_t h23 = packhf2(o2, o3);
    __half2 hv01 = *(__half2*)&h01;
    __half2 hv23 = *(__half2*)&h23;
    uint32_t l01 = packhf2(o0 - __half2float(hv01.x),
                           o1 - __half2float(hv01.y));
    uint32_t l23 = packhf2(o2 - __half2float(hv23.x),
                           o3 - __half2float(hv23.y));
    __half* row = g_a3f + (size_t)m * K3_1;
    uint2 H = {h01, h23}, L = {l01, l23};
    *(uint2*)(row + tid * 4)        = H;
    *(uint2*)(row + 1024 + tid * 4) = L;
    *(uint2*)(row + 2048 + tid * 4) = H;
}

// ---------------- weight transpose + fp16 split: T[n][3K] = [hi, hi, lo] --------
__global__ void k_tsplit(const float* __restrict__ W, int K, int N,
                         __half* __restrict__ T)
{
    __shared__ float t[32][33];
    int nb = blockIdx.x * 32, kb = blockIdx.y * 32;
    int x = threadIdx.x, y = threadIdx.y;   // 32 x 8
    #pragma unroll
    for (int i = 0; i < 32; i += 8) {
        int k = kb + y + i, n = nb + x;
        t[y + i][x] = (n < N) ? W[(size_t)k * N + n] : 0.f;
    }
    __syncthreads();
    #pragma unroll
    for (int i = 0; i < 32; i += 8) {
        int n = nb + y + i, k = kb + x;
        float v = t[x][y + i];
        __half h = __float2half_rn(v);
        __half l = __float2half_rn(v - __half2float(h));
        __half* row = T + (size_t)n * 3 * K;
        row[k]         = h;
        row[K + k]     = h;
        row[2 * K + k] = l;
    }
}

// ---------------- mma.sync fp16 GEMM (128x128 CTA, 64x64 warp, BK=64) -----------
// 128 threads = 4 warps (2m x 2n). Kext <= stride; nbase offsets the n-tiles.
// MODE 0: fused proj epilogue; MODE 1: C = result + ADD
#define GSTAGE 32768
#define GSMEM  (3 * GSTAGE)

template<int MODE>
__global__ void __launch_bounds__(128, 2)
k_gemm_f16(const __half* __restrict__ A, const __half* __restrict__ B,
           const float* __restrict__ ADD, float* __restrict__ C,
           int N, int strideA, int strideB, int Kext, int nbase)
{
    extern __shared__ char sm[];
    uint32_t smu = s2u(sm);
    int tid = threadIdx.x, wid = tid >> 5, lane = tid & 31;
    int n0 = nbase + blockIdx.x * 128, m0 = blockIdx.y * 128;
    int KT = Kext >> 6;

    auto issue = [&](int kt, int slot) {
        uint32_t st = smu + slot * GSTAGE;
        size_t k0 = (size_t)kt * 64;
        #pragma unroll
        for (int t = 0; t < 8; ++t) {
            int idx = tid + t * 128;
            int rw = idx >> 3, c = idx & 7;
            uint32_t sw = (uint32_t)(rw * 128) + (uint32_t)((c ^ (rw & 7)) << 4);
            cp16(st + sw, A + (size_t)(m0 + rw) * strideA + k0 + c * 8);
        }
        #pragma unroll
        for (int t = 0; t < 8; ++t) {
            int idx = tid + t * 128;
            int rw = idx >> 3, c = idx & 7;
            uint32_t sw = (uint32_t)(rw * 128) + (uint32_t)((c ^ (rw & 7)) << 4);
            cp16(st + 16384 + sw, B + (size_t)(n0 + rw) * strideB + k0 + c * 8);
        }
    };

    issue(0, 0); CP_COMMIT();
    issue(1, 1); CP_COMMIT();

    float d[4][8][4];
    #pragma unroll
    for (int i = 0; i < 4; i++)
        #pragma unroll
        for (int j = 0; j < 8; j++)
            #pragma unroll
            for (int e = 0; e < 4; e++) d[i][j][e] = 0.f;

    int mo = (wid >> 1) * 64, no = (wid & 1) * 64;

    for (int kt = 0; kt < KT; ++kt) {
        CP_WAIT1();
        __syncthreads();
        if (kt + 2 < KT) issue(kt + 2, (kt + 2) % 3);
        CP_COMMIT();

        uint32_t sA = smu + (kt % 3) * GSTAGE;
        uint32_t sB = sA + 16384;
        #pragma unroll
        for (int ks = 0; ks < 4; ++ks) {
            uint32_t afr[4][4], bfr[4][4];
            {
                int c = ks * 2 + (lane >> 4);
                #pragma unroll
                for (int ma = 0; ma < 4; ++ma) {
                    int r = mo + ma * 16 + (lane & 15);
                    ldm4(afr[ma], sA + (uint32_t)(r * 128) + (uint32_t)((c ^ (r & 7)) << 4));
                }
            }
            {
                int c = ks * 2 + ((lane >> 3) & 1);
                #pragma unroll
                for (int nb = 0; nb < 4; ++nb) {
                    int r = no + nb * 16 + (lane & 7) + (((lane >> 4) & 1) << 3);
                    ldm4(bfr[nb], sB + (uint32_t)(r * 128) + (uint32_t)((c ^ (r & 7)) << 4));
                }
            }
            #pragma unroll
            for (int mi = 0; mi < 4; ++mi)
                #pragma unroll
                for (int ni = 0; ni < 8; ++ni)
                    mma16816h(d[mi][ni], afr[mi], &bfr[ni >> 1][(ni & 1) * 2]);
        }
    }

    // epilogue
    #pragma unroll
    for (int mi = 0; mi < 4; ++mi) {
        int r0 = m0 + mo + mi * 16 + (lane >> 2);
        #pragma unroll
        for (int ni = 0; ni < 8; ++ni) {
            int col = n0 + no + ni * 8 + (lane & 3) * 2;
            #pragma unroll
            for (int half = 0; half < 2; ++half) {
                int row = r0 + half * 8;
                float2 v = {d[mi][ni][half * 2], d[mi][ni][half * 2 + 1]};
                if (MODE == 0) {
                    if (col < 2048) {
                        float2 o = {silu1(v.x), silu1(v.y)};
                        *(float2*)(g_xs + (size_t)row * 2048 + col) = o;
                    } else if (col < 4096) {
                        float2 o = {silu1(v.x), silu1(v.y)};
                        *(float2*)(g_sz + (size_t)row * 2048 + col - 2048) = o;
                    } else if (col < 4256) {
                        *(float2*)(g_tail + (size_t)row * 160 + col - 4096) = v;
                    }
                } else {
                    if (col < N) {
                        float2 a2 = *(const float2*)(ADD + (size_t)row * N + col);
                        v.x += a2.x; v.y += a2.y;
                        *(float2*)(C + (size_t)row * N + col) = v;
                    }
                }
            }
        }
    }
}

// ---------------- per-row prep (tail only) --------------------------------------
__global__ void __launch_bounds__(96) k_prep(const float* __restrict__ A_log,
        const float* __restrict__ dt_bias,
        const float* __restrict__ bcB, const float* __restrict__ bcC,
        const float* __restrict__ Bbias, const float* __restrict__ Cbias)
{
    int m = blockIdx.x, tid = threadIdx.x;
    const float* tail = g_tail + (size_t)m * 160;
    __shared__ float s_dts;

    int lane = tid & 31, wid = tid >> 5;
    if (wid == 0) {
        float b0 = tail[lane], b1 = tail[32 + lane];
        float ss = b0 * b0 + b1 * b1;
        #pragma unroll
        for (int o = 16; o; o >>= 1) ss += __shfl_xor_sync(0xffffffffu, ss, o);
        float r = rsqrtf(ss * (1.f / 64.f) + 1e-6f);
        g_Bc[(size_t)m * 64 + lane]      = b0 * r * bcB[lane]      + Bbias[lane];
        g_Bc[(size_t)m * 64 + 32 + lane] = b1 * r * bcB[32 + lane] + Bbias[32 + lane];
    } else if (wid == 1) {
        float b0 = tail[64 + lane], b1 = tail[96 + lane];
        float ss = b0 * b0 + b1 * b1;
        #pragma unroll
        for (int o = 16; o; o >>= 1) ss += __shfl_xor_sync(0xffffffffu, ss, o);
        float r = rsqrtf(ss * (1.f / 64.f) + 1e-6f);
        g_Cc[(size_t)m * 64 + lane]      = b0 * r * bcC[lane]      + Cbias[lane];
        g_Cc[(size_t)m * 64 + 32 + lane] = b1 * r * bcC[32 + lane] + Cbias[32 + lane];
    } else {
        float dt = 0.f;
        if (lane < 16) {
            float x = tail[128 + lane] + dt_bias[lane];
            dt = (x > 20.f) ? x : log1pf(expf(x));
            float lamr = tail[144 + lane];
            float lam = 1.f / (1.f + expf(-lamr));
            float a = expf(-expf(A_log[lane]) * dt);
            size_t o = ((size_t)m * 16 + lane) * 4;
            g_coef[o]     = a;
            g_coef[o + 1] = dt * lam;
            g_coef[o + 2] = dt * (1.f - lam) * a;
            g_coef[o + 3] = 0.f;
        }
        float s = dt;
        #pragma unroll
        for (int o = 16; o; o >>= 1) s += __shfl_xor_sync(0xffffffffu, s, o);
        if (lane == 0) s_dts = s * (1.f / 16.f);
    }
    __syncthreads();
    if (tid < 32)
        g_phi[(size_t)m * 32 + tid] = s_dts * g_theta[(size_t)m * 32 + tid];
}

// ---------------- 3-phase cumsum (phase 3 fused with RoPE) ----------------------
__global__ void k_cs_chunk()
{
    int b = blockIdx.x >> 6, ch = blockIdx.x & 63;
    int c = threadIdx.x;
    size_t base = (((size_t)b * 4096) + (size_t)ch * 64) * 32 + c;
    float acc = 0.f;
    #pragma unroll 8
    for (int l = 0; l < 64; ++l) {
        acc += g_phi[base + (size_t)l * 32];
        g_phi[base + (size_t)l * 32] = acc;
    }
    g_csum[((size_t)(b * 64 + ch)) * 32 + c] = acc;
}
__global__ void k_cs_scan()
{
    int tid = threadIdx.x;
    int b = tid >> 5, c = tid & 31;
    float acc = 0.f;
    #pragma unroll 8
    for (int ch = 0; ch < 64; ++ch) {
        size_t o = ((size_t)(b * 64 + ch)) * 32 + c;
        float t = g_csum[o];
        g_csum[o] = acc;
        acc += t;
    }
}
__global__ void k_cs_add_rope()
{
    int b = blockIdx.x >> 6, ch = blockIdx.x & 63;
    __shared__ float off[32];
    if (threadIdx.x < 32)
        off[threadIdx.x] = g_csum[((size_t)(b * 64 + ch)) * 32 + threadIdx.x];
    __syncthreads();
    size_t mbase = (size_t)b * 4096 + (size_t)ch * 64;
    for (int e = threadIdx.x; e < 2048; e += 256) {
        int r = e >> 5, c = e & 31;
        size_t m = mbase + r;
        float ph = g_phi[m * 32 + c] + off[c];
        float cc = cosf(ph), ss = sinf(ph);
        size_t o = m * 64 + c;
        float xr = g_Bc[o], xi = g_Bc[o + 32];
        g_Bc[o]      = xr * cc - xi * ss;
        g_Bc[o + 32] = xr * ss + xi * cc;
        xr = g_Cc[o]; xi = g_Cc[o + 32];
        g_Cc[o]      = xr * cc - xi * ss;
        g_Cc[o + 32] = xr * ss + xi * cc;
    }
}

// ---------------- SSD scan + gate + fp16 [hi,lo,hi] pack (4p x 8n) --------------
// grid 128 = (b:4, h:16, pg2:2); 128 threads: pq = tid>>3 (16), nsub = tid&7.
#define SCHUNK 32
#define ST2_F  8320
#define SCAN_SMEM ((2 * ST2_F + 2048) * 4)   // 74752 bytes

__global__ void __launch_bounds__(128) k_scan(const float* __restrict__ Dv)
{
    extern __shared__ float sf[];
    uint32_t smu = s2u(sf);
    int bx = blockIdx.x;
    int pg2 = bx & 1, h = (bx >> 1) & 15, b = bx >> 5;
    int tid = threadIdx.x;
    int nsub = tid & 7, pq = tid >> 3;
    size_t mb = (size_t)b * 4096;
    const float* Bg = g_Bc + mb * 64;
    const float* Cg = g_Cc + mb * 64;
    const float* Xg = g_xs + mb * 2048 + h * 128 + pg2 * 64;
    const float* Zg = g_sz + mb * 2048 + h * 128 + pg2 * 64;
    const float* Kg = g_coef + (mb * 16 + h) * 4;
    float Dh = Dv[h];
    int jbase = h * 128 + pg2 * 64;

    auto load_chunk = [&](int c, int slot) {
        int t0 = c * SCHUNK;
        uint32_t sb = smu + slot * ST2_F * 4;
        #pragma unroll
        for (int i = 0; i < 4; ++i) {
            int idx = tid + i * 128;
            int t = idx >> 4, seg = idx & 15;
            cp16(sb + (uint32_t)(t * 64 + seg * 4) * 4,
                 Bg + (size_t)(t0 + t) * 64 + seg * 4);
        }
        #pragma unroll
        for (int i = 0; i < 4; ++i) {
            int idx = tid + i * 128;
            int t = idx >> 4, seg = idx & 15;
            cp16(sb + (uint32_t)(2048 + t * 64 + seg * 4) * 4,
                 Cg + (size_t)(t0 + t) * 64 + seg * 4);
        }
        #pragma unroll
        for (int i = 0; i < 4; ++i) {
            int idx = tid + i * 128;
            int t = idx >> 4, seg = idx & 15;
            cp16(sb + (uint32_t)(4096 + t * 64 + seg * 4) * 4,
                 Xg + (size_t)(t0 + t) * 2048 + seg * 4);
        }
        #pragma unroll
        for (int i = 0; i < 4; ++i) {
            int idx = tid + i * 128;
            int t = idx >> 4, seg = idx & 15;
            cp16(sb + (uint32_t)(6144 + t * 64 + seg * 4) * 4,
                 Zg + (size_t)(t0 + t) * 2048 + seg * 4);
        }
        if (tid < SCHUNK)
            cp16(sb + (uint32_t)(8192 + tid * 4) * 4,
                 Kg + (size_t)(t0 + tid) * 64);
    };

    u64 s2[4][4], Bp2[4];
    #pragma unroll
    for (int p = 0; p < 4; ++p)
        #pragma unroll
        for (int i = 0; i < 4; ++i) s2[p][i] = 0ull;
    #pragma unroll
    for (int i = 0; i < 4; ++i) Bp2[i] = 0ull;
    float4 xprev = {0.f, 0.f, 0.f, 0.f};
    float alpha_prev = 0.f;
    float* ybuf = sf + 2 * ST2_F;

    load_chunk(0, 0); CP_COMMIT();
    load_chunk(1, 1); CP_COMMIT();

    const int NCHUNK = LL / SCHUNK;   // 128
    for (int c = 0; c < NCHUNK; ++c) {
        int slot = c & 1;
        const float* st = sf + slot * ST2_F;
        CP_WAIT1();
        __syncthreads();
        #pragma unroll 2
        for (int t = 0; t < SCHUNK; ++t) {
            ulonglong2 B01 = *(const ulonglong2*)(st + t * 64 + nsub * 8);
            ulonglong2 B23 = *(const ulonglong2*)(st + t * 64 + nsub * 8 + 4);
            ulonglong2 C01 = *(const ulonglong2*)(st + 2048 + t * 64 + nsub * 8);
            ulonglong2 C23 = *(const ulonglong2*)(st + 2048 + t * 64 + nsub * 8 + 4);
            float4 cf = *(const float4*)(st + 8192 + t * 4);
            float4 x4 = *(const float4*)(st + 4096 + t * 64 + pq * 4);
            u64 Bn[4] = {B01.x, B01.y, B23.x, B23.y};
            u64 Cn[4] = {C01.x, C01.y, C23.x, C23.y};

            float delta = fmaf(cf.x, alpha_prev, cf.z);
            u64 ca2 = pk2(cf.x, cf.x);
            u64 e2[4];
            e2[0] = pk2(delta * xprev.x, delta * xprev.x);
            e2[1] = pk2(delta * xprev.y, delta * xprev.y);
            e2[2] = pk2(delta * xprev.z, delta * xprev.z);
            e2[3] = pk2(delta * xprev.w, delta * xprev.w);

            u64 cb2 = 0ull;
            u64 acc2[4] = {0ull, 0ull, 0ull, 0ull};
            #pragma unroll
            for (int i = 0; i < 4; ++i) {
                cb2 = fma2_(Bn[i], Cn[i], cb2);
                #pragma unroll
                for (int p = 0; p < 4; ++p) {
                    s2[p][i] = fma2_(ca2, s2[p][i], mul2_(e2[p], Bp2[i]));
                    acc2[p] = fma2_(s2[p][i], Cn[i], acc2[p]);
                }
                Bp2[i] = Bn[i];
            }
            float a0l, a0h, a1l, a1h, a2l, a2h, a3l, a3h, cbl, cbh;
            upk2(a0l, a0h, acc2[0]); upk2(a1l, a1h, acc2[1]);
            upk2(a2l, a2h, acc2[2]); upk2(a3l, a3h, acc2[3]);
            upk2(cbl, cbh, cb2);
            u64 q01 = pk2(a0l + a0h, a1l + a1h);
            u64 q23 = pk2(a2l + a2h, a3l + a3h);
            float cb = cbl + cbh;
            #pragma unroll
            for (int o = 1; o < 8; o <<= 1) {
                q01 = add2_(q01, __shfl_xor_sync(0xffffffffu, q01, o));
                q23 = add2_(q23, __shfl_xor_sync(0xffffffffu, q23, o));
                cb += __shfl_xor_sync(0xffffffffu, cb, o);
            }
            if (nsub == 0) {
                float y0, y1, y2, y3;
                upk2(y0, y1, q01);
                upk2(y2, y3, q23);
                float axcb = cf.y * cb;
                float4 z4 = *(const float4*)(st + 6144 + t * 64 + pq * 4);
                float4 yo;
                yo.x = (y0 + x4.x * (axcb + Dh)) * z4.x;
                yo.y = (y1 + x4.y * (axcb + Dh)) * z4.y;
                yo.z = (y2 + x4.z * (axcb + Dh)) * z4.z;
                yo.w = (y3 + x4.w * (axcb + Dh)) * z4.w;
                *(float4*)(ybuf + t * 64 + pq * 4) = yo;
            }
            xprev = x4;
            alpha_prev = cf.y;
        }
        __syncthreads();
        #pragma unroll
        for (int i = 0; i < 4; ++i) {
            int idx = tid + i * 128;
            int t = idx >> 4, p0 = (idx & 15) * 4;
            float4 y4 = *(const float4*)(ybuf + t * 64 + p0);
            uint32_t h01 = packhf2(y4.x, y4.y);
            uint32_t h23 = packhf2(y4.z, y4.w);
            __half2 hv01 = *(__half2*)&h01;
            __half2 hv23 = *(__half2*)&h23;
            uint32_t l01 = packhf2(y4.x - __half2float(hv01.x),
                                   y4.y - __half2float(hv01.y));
            uint32_t l23 = packhf2(y4.z - __half2float(hv23.x),
                                   y4.w - __half2float(hv23.y));
            size_t row = mb + (size_t)c * SCHUNK + t;
            __half* rp = g_yz3f + row * K3_2 + jbase + p0;
            uint2 H = {h01, h23}, L = {l01, l23};
            *(uint2*)rp          = H;
            *(uint2*)(rp + 2048) = L;
            *(uint2*)(rp + 4096) = H;
        }
        if (c + 2 < NCHUNK) load_chunk(c + 2, slot);
        CP_COMMIT();
    }
}

// ---------------- host launcher --------------------------------------------------
template<typename T>
static T* sym_addr(const void* s)
{
    void* p = nullptr;
    cudaGetSymbolAddress(&p, s);
    return (T*)p;
}

extern "C" void kernel_launch(void* const* d_in, const int* in_sizes, int n_in,
                              void* d_out, int out_size)
{
    const float* u          = (const float*)d_in[0];
    const float* norm_scale = (const float*)d_in[1];
    const float* norm_bias  = (const float*)d_in[2];
    const float* in_proj_w  = (const float*)d_in[3];
    const float* A_log      = (const float*)d_in[4];
    const float* dt_bias    = (const float*)d_in[5];
    const float* bcB_scale  = (const float*)d_in[6];
    const float* bcC_scale  = (const float*)d_in[7];
    const float* B_bias     = (const float*)d_in[8];
    const float* C_bias     = (const float*)d_in[9];
    const float* theta_w    = (const float*)d_in[10];
    const float* Dv         = (const float*)d_in[11];
    const float* out_proj_w = (const float*)d_in[12];
    float* out = (float*)d_out;

    __half* p_a3f  = sym_addr<__half>(g_a3f);
    __half* p_yz3f = sym_addr<__half>(g_yz3f);
    __half* p_w1f  = sym_addr<__half>(g_w1f);
    __half* p_w2f  = sym_addr<__half>(g_w2f);

    static bool attr_done = false;
    if (!attr_done) {
        cudaFuncSetAttribute(k_gemm_f16<0>,
            cudaFuncAttributeMaxDynamicSharedMemorySize, GSMEM);
        cudaFuncSetAttribute(k_gemm_f16<1>,
            cudaFuncAttributeMaxDynamicSharedMemorySize, GSMEM);
        cudaFuncSetAttribute(k_scan,
            cudaFuncAttributeMaxDynamicSharedMemorySize, SCAN_SMEM);
        cudaFuncSetAttribute(k_theta,
            cudaFuncAttributeMaxDynamicSharedMemorySize, THETA_SMEM);
        attr_done = true;
    }

    // 1. theta = u @ theta_w (blocked, tw cached in smem)
    k_theta<<<MROWS / 128, 256, THETA_SMEM>>>(u, theta_w);
    // 2. layernorm + fp16 [hi,lo,hi] pack
    k_ln<<<MROWS, 256>>>(u, norm_scale, norm_bias);
    // 3. weight transpose + fp16 [hi,hi,lo] pack
    k_tsplit<<<dim3(NPAD1 / 32, DMODEL / 32), dim3(32, 8)>>>(
        in_proj_w, DMODEL, PROJ, p_w1f);
    k_tsplit<<<dim3(DMODEL / 32, DINNER / 32), dim3(32, 8)>>>(
        out_proj_w, DINNER, DMODEL, p_w2f);
    // 4a. proj GEMM main (cols 0..4095): K2 prefix = x . w_hi
    k_gemm_f16<0><<<dim3(32, MROWS / 128), 128, GSMEM>>>(
        p_a3f, p_w1f, nullptr, nullptr, PROJ, K3_1, K3_1, 2 * DMODEL, 0);
    // 4b. proj GEMM tail (cols 4096..4351): full K3 = high precision
    k_gemm_f16<0><<<dim3(2, MROWS / 128), 128, GSMEM>>>(
        p_a3f, p_w1f, nullptr, nullptr, PROJ, K3_1, K3_1, K3_1, 4096);
    // 5. tail prep
    k_prep<<<MROWS, 96>>>(A_log, dt_bias, bcB_scale, bcC_scale, B_bias, C_bias);
    // 6. cumsum(phi) + fused RoPE
    k_cs_chunk<<<BB * 64, 32>>>();
    k_cs_scan<<<1, 128>>>();
    k_cs_add_rope<<<BB * 64, 256>>>();
    // 7. SSD scan + gate + fp16 pack (4p x 8n; 128 blocks)
    k_scan<<<BB * NHEADS * 2, 128, SCAN_SMEM>>>(Dv);
    // 8. out GEMM: K2 prefix = yz . w_hi, + residual
    k_gemm_f16<1><<<dim3(DMODEL / 128, MROWS / 128), 128, GSMEM>>>(
        p_yz3f, p_w2f, u, out, DMODEL, K3_2, K3_2, 2 * DINNER, 0);
}